// round 1
// baseline (speedup 1.0000x reference)
#include <cuda_runtime.h>
#include <cstdint>

#define D 512
#define MAX_NODES 100000

// Scratch accumulator: agg[d] = sum_e w_e * h[src_e]  (fp32, in D_IN space)
__device__ float g_agg[(size_t)MAX_NODES * D];
// Index dtype flag: 1 if src/dst are int64, 0 if int32
__device__ int g_is64;

// ---------------------------------------------------------------------------
// Zero the accumulator
// ---------------------------------------------------------------------------
__global__ void zero_agg(int n4) {
    float4 z = make_float4(0.f, 0.f, 0.f, 0.f);
    float4* p = reinterpret_cast<float4*>(g_agg);
    for (int i = blockIdx.x * blockDim.x + threadIdx.x; i < n4;
         i += gridDim.x * blockDim.x)
        p[i] = z;
}

// ---------------------------------------------------------------------------
// Detect whether index arrays are int64 or int32.
// int64 little-endian values < 2^17 -> every odd 32-bit word is 0.
// ---------------------------------------------------------------------------
__global__ void detect_idx_dtype(const unsigned* __restrict__ src_words) {
    int all_zero = 1;
    for (int i = 1; i < 64; i += 2)
        if (src_words[i] != 0u) all_zero = 0;
    g_is64 = all_zero;
}

// ---------------------------------------------------------------------------
// Edge scatter: one warp per edge. 512 floats = 128 float4 = 4 per lane.
// red.global.add.v4.f32 (sm_90+) for vectorized atomic accumulation.
// ---------------------------------------------------------------------------
__global__ void edge_scatter(const float* __restrict__ h,
                             const float* __restrict__ ew,
                             const void* __restrict__ src_raw,
                             const void* __restrict__ dst_raw,
                             int E) {
    int gw = (int)((blockIdx.x * (unsigned)blockDim.x + threadIdx.x) >> 5);
    if (gw >= E) return;
    int lane = threadIdx.x & 31;

    long long s, d;
    if (g_is64) {
        s = reinterpret_cast<const long long*>(src_raw)[gw];
        d = reinterpret_cast<const long long*>(dst_raw)[gw];
    } else {
        s = reinterpret_cast<const int*>(src_raw)[gw];
        d = reinterpret_cast<const int*>(dst_raw)[gw];
    }
    float w = ew[gw];

    const float4* hs = reinterpret_cast<const float4*>(h + s * (long long)D);
    float4* ad = reinterpret_cast<float4*>(g_agg + d * (long long)D);

#pragma unroll
    for (int i = 0; i < 4; i++) {
        float4 v = hs[lane + 32 * i];
        v.x *= w; v.y *= w; v.z *= w; v.w *= w;
        asm volatile(
            "red.global.add.v4.f32 [%0], {%1, %2, %3, %4};"
            :: "l"(ad + lane + 32 * i),
               "f"(v.x), "f"(v.y), "f"(v.z), "f"(v.w)
            : "memory");
    }
}

// ---------------------------------------------------------------------------
// tf32 mma.sync GEMM:  out = relu( g_agg[M,512] @ W[512,512] )
// Block tile 128x128, BK=16, 256 threads (8 warps as 2(M) x 4(N)),
// warp tile 64x32, mma m16n8k8: 4 m-tiles x 4 n-tiles per warp.
// ---------------------------------------------------------------------------
#define BM 128
#define BN 128
#define BK 16
#define AS_STRIDE 20   // 16 + 4 pad  -> conflict-free frag reads
#define BS_STRIDE 132  // 128 + 4 pad -> conflict-free frag reads

__device__ __forceinline__ unsigned f2tf(float x) {
    unsigned u;
    asm("cvt.rna.tf32.f32 %0, %1;" : "=r"(u) : "f"(x));
    return u;
}

__global__ __launch_bounds__(256, 2)
void gemm_relu(const float* __restrict__ Bmat, float* __restrict__ out, int M) {
    __shared__ unsigned As[BM * AS_STRIDE];
    __shared__ unsigned Bs[BK * BS_STRIDE];

    const int tid  = threadIdx.x;
    const int warp = tid >> 5;
    const int lane = tid & 31;
    const int wm = warp & 1;          // 2 warps along M
    const int wn = warp >> 1;         // 4 warps along N
    const int warpRow = wm * 64;
    const int warpCol = wn * 32;
    const int blockRow = blockIdx.y * BM;
    const int blockCol = blockIdx.x * BN;
    const float* A = g_agg;

    float c[4][4][4];
#pragma unroll
    for (int i = 0; i < 4; i++)
#pragma unroll
        for (int j = 0; j < 4; j++)
#pragma unroll
            for (int q = 0; q < 4; q++) c[i][j][q] = 0.f;

    float4 aReg[2], bReg[2];

    // --- global tile loaders (each thread: 2 float4 for A, 2 for B) ---
    auto loadTile = [&](int kt) {
#pragma unroll
        for (int wch = 0; wch < 2; wch++) {
            int idx = tid + wch * 256;
            // A tile: 128 rows x 16 cols -> 512 float4 (4 float4 per row)
            int ra = idx >> 2, ca = (idx & 3) * 4;
            int grow = blockRow + ra;
            if (grow < M)
                aReg[wch] = *reinterpret_cast<const float4*>(
                    A + (size_t)grow * D + kt * BK + ca);
            else
                aReg[wch] = make_float4(0.f, 0.f, 0.f, 0.f);
            // B tile: 16 rows x 128 cols -> 512 float4 (32 float4 per row)
            int rb = idx >> 5, cb = (idx & 31) * 4;
            bReg[wch] = *reinterpret_cast<const float4*>(
                Bmat + (size_t)(kt * BK + rb) * D + blockCol + cb);
        }
    };
    auto storeTile = [&]() {
#pragma unroll
        for (int wch = 0; wch < 2; wch++) {
            int idx = tid + wch * 256;
            int ra = idx >> 2, ca = (idx & 3) * 4;
            unsigned* da = &As[ra * AS_STRIDE + ca];
            float4 v = aReg[wch];
            da[0] = f2tf(v.x); da[1] = f2tf(v.y);
            da[2] = f2tf(v.z); da[3] = f2tf(v.w);
            int rb = idx >> 5, cb = (idx & 31) * 4;
            unsigned* db = &Bs[rb * BS_STRIDE + cb];
            float4 u = bReg[wch];
            db[0] = f2tf(u.x); db[1] = f2tf(u.y);
            db[2] = f2tf(u.z); db[3] = f2tf(u.w);
        }
    };

    const int KT = D / BK;  // 32
    loadTile(0);

    for (int kt = 0; kt < KT; kt++) {
        storeTile();
        __syncthreads();
        if (kt + 1 < KT) loadTile(kt + 1);  // prefetch next tile into regs

#pragma unroll
        for (int ks = 0; ks < 2; ks++) {
            const int k0 = ks * 8;
            unsigned af[4][4], bf[4][2];
            const int kk = k0 + (lane & 3);
#pragma unroll
            for (int i = 0; i < 4; i++) {
                int r = warpRow + i * 16 + (lane >> 2);
                af[i][0] = As[r * AS_STRIDE + kk];
                af[i][1] = As[(r + 8) * AS_STRIDE + kk];
                af[i][2] = As[r * AS_STRIDE + kk + 4];
                af[i][3] = As[(r + 8) * AS_STRIDE + kk + 4];
            }
#pragma unroll
            for (int j = 0; j < 4; j++) {
                int col = warpCol + j * 8 + (lane >> 2);
                bf[j][0] = Bs[kk * BS_STRIDE + col];
                bf[j][1] = Bs[(kk + 4) * BS_STRIDE + col];
            }
#pragma unroll
            for (int i = 0; i < 4; i++)
#pragma unroll
                for (int j = 0; j < 4; j++) {
                    asm volatile(
                        "mma.sync.aligned.m16n8k8.row.col.f32.tf32.tf32.f32 "
                        "{%0,%1,%2,%3}, {%4,%5,%6,%7}, {%8,%9}, {%0,%1,%2,%3};"
                        : "+f"(c[i][j][0]), "+f"(c[i][j][1]),
                          "+f"(c[i][j][2]), "+f"(c[i][j][3])
                        : "r"(af[i][0]), "r"(af[i][1]),
                          "r"(af[i][2]), "r"(af[i][3]),
                          "r"(bf[j][0]), "r"(bf[j][1]));
                }
        }
        __syncthreads();
    }

    // Epilogue: ReLU + store
#pragma unroll
    for (int i = 0; i < 4; i++) {
        int r0 = blockRow + warpRow + i * 16 + (lane >> 2);
        int r1 = r0 + 8;
#pragma unroll
        for (int j = 0; j < 4; j++) {
            int col = blockCol + warpCol + j * 8 + (lane & 3) * 2;
            if (r0 < M) {
                float2 v;
                v.x = fmaxf(c[i][j][0], 0.f);
                v.y = fmaxf(c[i][j][1], 0.f);
                *reinterpret_cast<float2*>(out + (size_t)r0 * D + col) = v;
            }
            if (r1 < M) {
                float2 v;
                v.x = fmaxf(c[i][j][2], 0.f);
                v.y = fmaxf(c[i][j][3], 0.f);
                *reinterpret_cast<float2*>(out + (size_t)r1 * D + col) = v;
            }
        }
    }
}

// ---------------------------------------------------------------------------
// kernel_launch
// inputs: h [N*512] f32, weight [512*512] f32, edge_weight [E] f32,
//         src [E] int, dst [E] int   output: [N*512] f32
// ---------------------------------------------------------------------------
extern "C" void kernel_launch(void* const* d_in, const int* in_sizes, int n_in,
                              void* d_out, int out_size) {
    const float* h  = (const float*)d_in[0];
    const float* Wt = (const float*)d_in[1];
    const float* ew = (const float*)d_in[2];
    const void* src = d_in[3];
    const void* dst = d_in[4];
    float* out = (float*)d_out;

    int M = in_sizes[0] / D;
    int E = in_sizes[2];

    // 1. zero accumulator
    int n4 = M * (D / 4);
    zero_agg<<<2048, 256>>>(n4);

    // 2. detect index dtype (int32 vs int64)
    detect_idx_dtype<<<1, 1>>>((const unsigned*)src);

    // 3. edge scatter: one warp per edge
    long long total_threads = (long long)E * 32;
    int blocks = (int)((total_threads + 255) / 256);
    edge_scatter<<<blocks, 256>>>(h, ew, src, dst, E);

    // 4. GEMM + ReLU: out = relu(agg @ W)
    dim3 grid(D / BN, (M + BM - 1) / BM);
    gemm_relu<<<grid, 256>>>(Wt, out, M);
}

// round 2
// speedup vs baseline: 1.5688x; 1.5688x over previous
#include <cuda_runtime.h>
#include <cstdint>

#define D 512
#define MAX_NODES 100000
#define MAX_E 2000000

// Scratch: agg[n] = sum_e w_e * h[src_e]  (fp32, D_IN space)
__device__ float g_agg[(size_t)MAX_NODES * D];
__device__ int g_is64;
// CSR-by-dst structures
__device__ int   g_cnt[MAX_NODES];
__device__ int   g_off[MAX_NODES + 1];
__device__ int   g_cur[MAX_NODES];
__device__ int   g_srcs[MAX_E];
__device__ float g_ws[MAX_E];

// ---------------------------------------------------------------------------
// Detect whether index arrays are int64 or int32 (odd 32-bit words all zero).
// ---------------------------------------------------------------------------
__global__ void detect_idx_dtype(const unsigned* __restrict__ src_words) {
    int all_zero = 1;
    for (int i = 1; i < 64; i += 2)
        if (src_words[i] != 0u) all_zero = 0;
    g_is64 = all_zero;
}

__global__ void zero_cnt(int M) {
    int i = blockIdx.x * blockDim.x + threadIdx.x;
    if (i < M) g_cnt[i] = 0;
}

// ---------------------------------------------------------------------------
// Histogram of dst
// ---------------------------------------------------------------------------
__global__ void hist_dst(const void* __restrict__ dst_raw, int E) {
    int e = blockIdx.x * blockDim.x + threadIdx.x;
    if (e >= E) return;
    int d = g_is64 ? (int)reinterpret_cast<const long long*>(dst_raw)[e]
                   : reinterpret_cast<const int*>(dst_raw)[e];
    atomicAdd(&g_cnt[d], 1);
}

// ---------------------------------------------------------------------------
// Single-CTA exclusive scan of g_cnt[0..M) -> g_off, g_cur. 1024 threads.
// ---------------------------------------------------------------------------
__global__ void scan_cnt(int M, int E) {
    __shared__ int wsum[32];
    const int tid = threadIdx.x, lane = tid & 31, wid = tid >> 5;
    const int chunk = (M + 1023) >> 10;
    const int beg = tid * chunk;
    const int end = min(beg + chunk, M);

    int s = 0;
    for (int i = beg; i < end; i++) s += g_cnt[i];

    // inclusive warp scan of per-thread sums
    int v = s;
#pragma unroll
    for (int d = 1; d < 32; d <<= 1) {
        int t = __shfl_up_sync(0xffffffffu, v, d);
        if (lane >= d) v += t;
    }
    if (lane == 31) wsum[wid] = v;
    __syncthreads();
    if (wid == 0) {
        int w = wsum[lane];
#pragma unroll
        for (int d = 1; d < 32; d <<= 1) {
            int t = __shfl_up_sync(0xffffffffu, w, d);
            if (lane >= d) w += t;
        }
        wsum[lane] = w;  // inclusive across warps
    }
    __syncthreads();

    int base = (wid > 0 ? wsum[wid - 1] : 0) + (v - s);  // exclusive prefix
    int run = base;
    for (int i = beg; i < end; i++) {
        g_off[i] = run;
        g_cur[i] = run;
        run += g_cnt[i];
    }
    if (tid == 0) g_off[M] = E;
}

// ---------------------------------------------------------------------------
// Reorder edges into dst-grouped arrays
// ---------------------------------------------------------------------------
__global__ void reorder_edges(const void* __restrict__ src_raw,
                              const void* __restrict__ dst_raw,
                              const float* __restrict__ ew, int E) {
    int e = blockIdx.x * blockDim.x + threadIdx.x;
    if (e >= E) return;
    int s, d;
    if (g_is64) {
        s = (int)reinterpret_cast<const long long*>(src_raw)[e];
        d = (int)reinterpret_cast<const long long*>(dst_raw)[e];
    } else {
        s = reinterpret_cast<const int*>(src_raw)[e];
        d = reinterpret_cast<const int*>(dst_raw)[e];
    }
    int pos = atomicAdd(&g_cur[d], 1);
    g_srcs[pos] = s;
    g_ws[pos] = ew[e];
}

// ---------------------------------------------------------------------------
// Gather: one warp per dst node, register-resident accumulation, write once.
// Edge-unrolled x2 -> 8 independent float4 loads in flight per thread.
// ---------------------------------------------------------------------------
__global__ void gather_agg(const float* __restrict__ h, int M) {
    int node = (int)((blockIdx.x * (unsigned)blockDim.x + threadIdx.x) >> 5);
    if (node >= M) return;
    const int lane = threadIdx.x & 31;
    const int beg = g_off[node];
    const int end = g_off[node + 1];

    float4 a0 = make_float4(0.f, 0.f, 0.f, 0.f), a1 = a0, a2 = a0, a3 = a0;

    int e = beg;
    for (; e + 1 < end; e += 2) {
        int s0 = g_srcs[e], s1 = g_srcs[e + 1];
        float w0 = g_ws[e], w1 = g_ws[e + 1];
        const float4* p0 = reinterpret_cast<const float4*>(h + (size_t)s0 * D);
        const float4* p1 = reinterpret_cast<const float4*>(h + (size_t)s1 * D);
        float4 v00 = p0[lane], v01 = p0[lane + 32],
               v02 = p0[lane + 64], v03 = p0[lane + 96];
        float4 v10 = p1[lane], v11 = p1[lane + 32],
               v12 = p1[lane + 64], v13 = p1[lane + 96];
        a0.x += v00.x * w0; a0.y += v00.y * w0; a0.z += v00.z * w0; a0.w += v00.w * w0;
        a1.x += v01.x * w0; a1.y += v01.y * w0; a1.z += v01.z * w0; a1.w += v01.w * w0;
        a2.x += v02.x * w0; a2.y += v02.y * w0; a2.z += v02.z * w0; a2.w += v02.w * w0;
        a3.x += v03.x * w0; a3.y += v03.y * w0; a3.z += v03.z * w0; a3.w += v03.w * w0;
        a0.x += v10.x * w1; a0.y += v10.y * w1; a0.z += v10.z * w1; a0.w += v10.w * w1;
        a1.x += v11.x * w1; a1.y += v11.y * w1; a1.z += v11.z * w1; a1.w += v11.w * w1;
        a2.x += v12.x * w1; a2.y += v12.y * w1; a2.z += v12.z * w1; a2.w += v12.w * w1;
        a3.x += v13.x * w1; a3.y += v13.y * w1; a3.z += v13.z * w1; a3.w += v13.w * w1;
    }
    if (e < end) {
        int s0 = g_srcs[e];
        float w0 = g_ws[e];
        const float4* p0 = reinterpret_cast<const float4*>(h + (size_t)s0 * D);
        float4 v00 = p0[lane], v01 = p0[lane + 32],
               v02 = p0[lane + 64], v03 = p0[lane + 96];
        a0.x += v00.x * w0; a0.y += v00.y * w0; a0.z += v00.z * w0; a0.w += v00.w * w0;
        a1.x += v01.x * w0; a1.y += v01.y * w0; a1.z += v01.z * w0; a1.w += v01.w * w0;
        a2.x += v02.x * w0; a2.y += v02.y * w0; a2.z += v02.z * w0; a2.w += v02.w * w0;
        a3.x += v03.x * w0; a3.y += v03.y * w0; a3.z += v03.z * w0; a3.w += v03.w * w0;
    }

    float4* o = reinterpret_cast<float4*>(g_agg + (size_t)node * D);
    o[lane] = a0; o[lane + 32] = a1; o[lane + 64] = a2; o[lane + 96] = a3;
}

// ---------------------------------------------------------------------------
// tf32 mma.sync GEMM:  out = relu( g_agg[M,512] @ W[512,512] )   (unchanged)
// ---------------------------------------------------------------------------
#define BM 128
#define BN 128
#define BK 16
#define AS_STRIDE 20
#define BS_STRIDE 132

__device__ __forceinline__ unsigned f2tf(float x) {
    unsigned u;
    asm("cvt.rna.tf32.f32 %0, %1;" : "=r"(u) : "f"(x));
    return u;
}

__global__ __launch_bounds__(256, 2)
void gemm_relu(const float* __restrict__ Bmat, float* __restrict__ out, int M) {
    __shared__ unsigned As[BM * AS_STRIDE];
    __shared__ unsigned Bs[BK * BS_STRIDE];

    const int tid  = threadIdx.x;
    const int warp = tid >> 5;
    const int lane = tid & 31;
    const int wm = warp & 1;
    const int wn = warp >> 1;
    const int warpRow = wm * 64;
    const int warpCol = wn * 32;
    const int blockRow = blockIdx.y * BM;
    const int blockCol = blockIdx.x * BN;
    const float* A = g_agg;

    float c[4][4][4];
#pragma unroll
    for (int i = 0; i < 4; i++)
#pragma unroll
        for (int j = 0; j < 4; j++)
#pragma unroll
            for (int q = 0; q < 4; q++) c[i][j][q] = 0.f;

    float4 aReg[2], bReg[2];

    auto loadTile = [&](int kt) {
#pragma unroll
        for (int wch = 0; wch < 2; wch++) {
            int idx = tid + wch * 256;
            int ra = idx >> 2, ca = (idx & 3) * 4;
            int grow = blockRow + ra;
            if (grow < M)
                aReg[wch] = *reinterpret_cast<const float4*>(
                    A + (size_t)grow * D + kt * BK + ca);
            else
                aReg[wch] = make_float4(0.f, 0.f, 0.f, 0.f);
            int rb = idx >> 5, cb = (idx & 31) * 4;
            bReg[wch] = *reinterpret_cast<const float4*>(
                Bmat + (size_t)(kt * BK + rb) * D + blockCol + cb);
        }
    };
    auto storeTile = [&]() {
#pragma unroll
        for (int wch = 0; wch < 2; wch++) {
            int idx = tid + wch * 256;
            int ra = idx >> 2, ca = (idx & 3) * 4;
            unsigned* da = &As[ra * AS_STRIDE + ca];
            float4 v = aReg[wch];
            da[0] = f2tf(v.x); da[1] = f2tf(v.y);
            da[2] = f2tf(v.z); da[3] = f2tf(v.w);
            int rb = idx >> 5, cb = (idx & 31) * 4;
            unsigned* db = &Bs[rb * BS_STRIDE + cb];
            float4 u = bReg[wch];
            db[0] = f2tf(u.x); db[1] = f2tf(u.y);
            db[2] = f2tf(u.z); db[3] = f2tf(u.w);
        }
    };

    const int KT = D / BK;
    loadTile(0);

    for (int kt = 0; kt < KT; kt++) {
        storeTile();
        __syncthreads();
        if (kt + 1 < KT) loadTile(kt + 1);

#pragma unroll
        for (int ks = 0; ks < 2; ks++) {
            const int k0 = ks * 8;
            unsigned af[4][4], bf[4][2];
            const int kk = k0 + (lane & 3);
#pragma unroll
            for (int i = 0; i < 4; i++) {
                int r = warpRow + i * 16 + (lane >> 2);
                af[i][0] = As[r * AS_STRIDE + kk];
                af[i][1] = As[(r + 8) * AS_STRIDE + kk];
                af[i][2] = As[r * AS_STRIDE + kk + 4];
                af[i][3] = As[(r + 8) * AS_STRIDE + kk + 4];
            }
#pragma unroll
            for (int j = 0; j < 4; j++) {
                int col = warpCol + j * 8 + (lane >> 2);
                bf[j][0] = Bs[kk * BS_STRIDE + col];
                bf[j][1] = Bs[(kk + 4) * BS_STRIDE + col];
            }
#pragma unroll
            for (int i = 0; i < 4; i++)
#pragma unroll
                for (int j = 0; j < 4; j++) {
                    asm volatile(
                        "mma.sync.aligned.m16n8k8.row.col.f32.tf32.tf32.f32 "
                        "{%0,%1,%2,%3}, {%4,%5,%6,%7}, {%8,%9}, {%0,%1,%2,%3};"
                        : "+f"(c[i][j][0]), "+f"(c[i][j][1]),
                          "+f"(c[i][j][2]), "+f"(c[i][j][3])
                        : "r"(af[i][0]), "r"(af[i][1]),
                          "r"(af[i][2]), "r"(af[i][3]),
                          "r"(bf[j][0]), "r"(bf[j][1]));
                }
        }
        __syncthreads();
    }

#pragma unroll
    for (int i = 0; i < 4; i++) {
        int r0 = blockRow + warpRow + i * 16 + (lane >> 2);
        int r1 = r0 + 8;
#pragma unroll
        for (int j = 0; j < 4; j++) {
            int col = blockCol + warpCol + j * 8 + (lane & 3) * 2;
            if (r0 < M) {
                float2 v;
                v.x = fmaxf(c[i][j][0], 0.f);
                v.y = fmaxf(c[i][j][1], 0.f);
                *reinterpret_cast<float2*>(out + (size_t)r0 * D + col) = v;
            }
            if (r1 < M) {
                float2 v;
                v.x = fmaxf(c[i][j][2], 0.f);
                v.y = fmaxf(c[i][j][3], 0.f);
                *reinterpret_cast<float2*>(out + (size_t)r1 * D + col) = v;
            }
        }
    }
}

// ---------------------------------------------------------------------------
// kernel_launch
// ---------------------------------------------------------------------------
extern "C" void kernel_launch(void* const* d_in, const int* in_sizes, int n_in,
                              void* d_out, int out_size) {
    const float* h  = (const float*)d_in[0];
    const float* Wt = (const float*)d_in[1];
    const float* ew = (const float*)d_in[2];
    const void* src = d_in[3];
    const void* dst = d_in[4];
    float* out = (float*)d_out;

    int M = in_sizes[0] / D;
    int E = in_sizes[2];

    detect_idx_dtype<<<1, 1>>>((const unsigned*)src);
    zero_cnt<<<(M + 255) / 256, 256>>>(M);
    hist_dst<<<(E + 255) / 256, 256>>>(dst, E);
    scan_cnt<<<1, 1024>>>(M, E);
    reorder_edges<<<(E + 255) / 256, 256>>>(src, dst, ew, E);

    // gather: one warp per node
    long long gthreads = (long long)M * 32;
    gather_agg<<<(int)((gthreads + 255) / 256), 256>>>(h, M);

    dim3 grid(D / BN, (M + BM - 1) / BM);
    gemm_relu<<<grid, 256>>>(Wt, out, M);
}

// round 4
// speedup vs baseline: 1.8567x; 1.1835x over previous
#include <cuda_runtime.h>
#include <cstdint>

#define D 512
#define MAX_NODES 100000
#define MAX_E 2000000
#define SCAN_TILE 1024
#define MAX_SCAN_BLOCKS 128

// Scratch: agg[n] = sum_e w_e * h[src_e]  (fp32, D_IN space)
__device__ float g_agg[(size_t)MAX_NODES * D];
__device__ int g_is64;
// CSR-by-dst structures
__device__ int   g_cnt[MAX_NODES];
__device__ int   g_off[MAX_NODES + 1];
__device__ int   g_cur[MAX_NODES];
__device__ int   g_srcs[MAX_E];
__device__ float g_ws[MAX_E];
__device__ int   g_bsum[MAX_SCAN_BLOCKS];

// ---------------------------------------------------------------------------
// Detect whether index arrays are int64 or int32 (odd 32-bit words all zero).
// ---------------------------------------------------------------------------
__global__ void detect_idx_dtype(const unsigned* __restrict__ src_words) {
    int all_zero = 1;
    for (int i = 1; i < 64; i += 2)
        if (src_words[i] != 0u) all_zero = 0;
    g_is64 = all_zero;
}

__global__ void zero_cnt(int M) {
    int i = blockIdx.x * blockDim.x + threadIdx.x;
    if (i < M) g_cnt[i] = 0;
}

// ---------------------------------------------------------------------------
// Histogram of dst
// ---------------------------------------------------------------------------
__global__ void hist_dst(const void* __restrict__ dst_raw, int E) {
    int e = blockIdx.x * blockDim.x + threadIdx.x;
    if (e >= E) return;
    int d = g_is64 ? (int)reinterpret_cast<const long long*>(dst_raw)[e]
                   : reinterpret_cast<const int*>(dst_raw)[e];
    atomicAdd(&g_cnt[d], 1);
}

// ---------------------------------------------------------------------------
// Multi-block exclusive scan, phase 1: each block scans SCAN_TILE elements
// of g_cnt into g_off (block-local exclusive), writes block total to g_bsum.
// ---------------------------------------------------------------------------
__global__ void scan_phase1(int M) {
    __shared__ int wsum[32];
    const int tid = threadIdx.x, lane = tid & 31, wid = tid >> 5;
    const int gi = blockIdx.x * SCAN_TILE + tid;

    int x = (gi < M) ? g_cnt[gi] : 0;

    // inclusive warp scan
    int v = x;
#pragma unroll
    for (int d = 1; d < 32; d <<= 1) {
        int t = __shfl_up_sync(0xffffffffu, v, d);
        if (lane >= d) v += t;
    }
    if (lane == 31) wsum[wid] = v;
    __syncthreads();
    if (wid == 0) {
        int w = wsum[lane];
#pragma unroll
        for (int d = 1; d < 32; d <<= 1) {
            int t = __shfl_up_sync(0xffffffffu, w, d);
            if (lane >= d) w += t;
        }
        wsum[lane] = w;
    }
    __syncthreads();

    int excl = (v - x) + (wid > 0 ? wsum[wid - 1] : 0);
    if (gi < M) g_off[gi] = excl;
    if (tid == SCAN_TILE - 1) g_bsum[blockIdx.x] = excl + x;
}

// ---------------------------------------------------------------------------
// Phase 2: single warp exclusive-scans the block sums (<=128 of them).
// ---------------------------------------------------------------------------
__global__ void scan_phase2(int nblocks) {
    const int lane = threadIdx.x;  // 32 threads
    int run = 0;
    for (int base = 0; base < nblocks; base += 32) {
        int i = base + lane;
        int x = (i < nblocks) ? g_bsum[i] : 0;
        int v = x;
#pragma unroll
        for (int d = 1; d < 32; d <<= 1) {
            int t = __shfl_up_sync(0xffffffffu, v, d);
            if (lane >= d) v += t;
        }
        if (i < nblocks) g_bsum[i] = run + (v - x);
        run += __shfl_sync(0xffffffffu, v, 31);
    }
}

// ---------------------------------------------------------------------------
// Phase 3: add block prefix, materialize g_off and g_cur, cap with E.
// ---------------------------------------------------------------------------
__global__ void scan_phase3(int M, int E) {
    const int gi = blockIdx.x * SCAN_TILE + threadIdx.x;
    if (gi < M) {
        int o = g_off[gi] + g_bsum[blockIdx.x];
        g_off[gi] = o;
        g_cur[gi] = o;
    }
    if (gi == 0) g_off[M] = E;
}

// ---------------------------------------------------------------------------
// Reorder edges into dst-grouped arrays
// ---------------------------------------------------------------------------
__global__ void reorder_edges(const void* __restrict__ src_raw,
                              const void* __restrict__ dst_raw,
                              const float* __restrict__ ew, int E) {
    int e = blockIdx.x * blockDim.x + threadIdx.x;
    if (e >= E) return;
    int s, d;
    if (g_is64) {
        s = (int)reinterpret_cast<const long long*>(src_raw)[e];
        d = (int)reinterpret_cast<const long long*>(dst_raw)[e];
    } else {
        s = reinterpret_cast<const int*>(src_raw)[e];
        d = reinterpret_cast<const int*>(dst_raw)[e];
    }
    int pos = atomicAdd(&g_cur[d], 1);
    g_srcs[pos] = s;
    g_ws[pos] = ew[e];
}

// ---------------------------------------------------------------------------
// Gather: one warp per dst node, register-resident accumulation, write once.
// ---------------------------------------------------------------------------
__global__ void gather_agg(const float* __restrict__ h, int M) {
    int node = (int)((blockIdx.x * (unsigned)blockDim.x + threadIdx.x) >> 5);
    if (node >= M) return;
    const int lane = threadIdx.x & 31;
    const int beg = g_off[node];
    const int end = g_off[node + 1];

    float4 a0 = make_float4(0.f, 0.f, 0.f, 0.f), a1 = a0, a2 = a0, a3 = a0;

    int e = beg;
    for (; e + 1 < end; e += 2) {
        int s0 = g_srcs[e], s1 = g_srcs[e + 1];
        float w0 = g_ws[e], w1 = g_ws[e + 1];
        const float4* p0 = reinterpret_cast<const float4*>(h + (size_t)s0 * D);
        const float4* p1 = reinterpret_cast<const float4*>(h + (size_t)s1 * D);
        float4 v00 = p0[lane], v01 = p0[lane + 32],
               v02 = p0[lane + 64], v03 = p0[lane + 96];
        float4 v10 = p1[lane], v11 = p1[lane + 32],
               v12 = p1[lane + 64], v13 = p1[lane + 96];
        a0.x += v00.x * w0; a0.y += v00.y * w0; a0.z += v00.z * w0; a0.w += v00.w * w0;
        a1.x += v01.x * w0; a1.y += v01.y * w0; a1.z += v01.z * w0; a1.w += v01.w * w0;
        a2.x += v02.x * w0; a2.y += v02.y * w0; a2.z += v02.z * w0; a2.w += v02.w * w0;
        a3.x += v03.x * w0; a3.y += v03.y * w0; a3.z += v03.z * w0; a3.w += v03.w * w0;
        a0.x += v10.x * w1; a0.y += v10.y * w1; a0.z += v10.z * w1; a0.w += v10.w * w1;
        a1.x += v11.x * w1; a1.y += v11.y * w1; a1.z += v11.z * w1; a1.w += v11.w * w1;
        a2.x += v12.x * w1; a2.y += v12.y * w1; a2.z += v12.z * w1; a2.w += v12.w * w1;
        a3.x += v13.x * w1; a3.y += v13.y * w1; a3.z += v13.z * w1; a3.w += v13.w * w1;
    }
    if (e < end) {
        int s0 = g_srcs[e];
        float w0 = g_ws[e];
        const float4* p0 = reinterpret_cast<const float4*>(h + (size_t)s0 * D);
        float4 v00 = p0[lane], v01 = p0[lane + 32],
               v02 = p0[lane + 64], v03 = p0[lane + 96];
        a0.x += v00.x * w0; a0.y += v00.y * w0; a0.z += v00.z * w0; a0.w += v00.w * w0;
        a1.x += v01.x * w0; a1.y += v01.y * w0; a1.z += v01.z * w0; a1.w += v01.w * w0;
        a2.x += v02.x * w0; a2.y += v02.y * w0; a2.z += v02.z * w0; a2.w += v02.w * w0;
        a3.x += v03.x * w0; a3.y += v03.y * w0; a3.z += v03.z * w0; a3.w += v03.w * w0;
    }

    float4* o = reinterpret_cast<float4*>(g_agg + (size_t)node * D);
    o[lane] = a0; o[lane + 32] = a1; o[lane + 64] = a2; o[lane + 96] = a3;
}

// ---------------------------------------------------------------------------
// tf32 mma.sync GEMM:  out = relu( g_agg[M,512] @ W[512,512] )
// ---------------------------------------------------------------------------
#define BM 128
#define BN 128
#define BK 16
#define AS_STRIDE 20
#define BS_STRIDE 132

__device__ __forceinline__ unsigned f2tf(float x) {
    unsigned u;
    asm("cvt.rna.tf32.f32 %0, %1;" : "=r"(u) : "f"(x));
    return u;
}

__global__ __launch_bounds__(256, 2)
void gemm_relu(const float* __restrict__ Bmat, float* __restrict__ out, int M) {
    __shared__ unsigned As[BM * AS_STRIDE];
    __shared__ unsigned Bs[BK * BS_STRIDE];

    const int tid  = threadIdx.x;
    const int warp = tid >> 5;
    const int lane = tid & 31;
    const int wm = warp & 1;
    const int wn = warp >> 1;
    const int warpRow = wm * 64;
    const int warpCol = wn * 32;
    const int blockRow = blockIdx.y * BM;
    const int blockCol = blockIdx.x * BN;
    const float* A = g_agg;

    float c[4][4][4];
#pragma unroll
    for (int i = 0; i < 4; i++)
#pragma unroll
        for (int j = 0; j < 4; j++)
#pragma unroll
            for (int q = 0; q < 4; q++) c[i][j][q] = 0.f;

    float4 aReg[2], bReg[2];

    auto loadTile = [&](int kt) {
#pragma unroll
        for (int wch = 0; wch < 2; wch++) {
            int idx = tid + wch * 256;
            int ra = idx >> 2, ca = (idx & 3) * 4;
            int grow = blockRow + ra;
            if (grow < M)
                aReg[wch] = *reinterpret_cast<const float4*>(
                    A + (size_t)grow * D + kt * BK + ca);
            else
                aReg[wch] = make_float4(0.f, 0.f, 0.f, 0.f);
            int rb = idx >> 5, cb = (idx & 31) * 4;
            bReg[wch] = *reinterpret_cast<const float4*>(
                Bmat + (size_t)(kt * BK + rb) * D + blockCol + cb);
        }
    };
    auto storeTile = [&]() {
#pragma unroll
        for (int wch = 0; wch < 2; wch++) {
            int idx = tid + wch * 256;
            int ra = idx >> 2, ca = (idx & 3) * 4;
            unsigned* da = &As[ra * AS_STRIDE + ca];
            float4 v = aReg[wch];
            da[0] = f2tf(v.x); da[1] = f2tf(v.y);
            da[2] = f2tf(v.z); da[3] = f2tf(v.w);
            int rb = idx >> 5, cb = (idx & 31) * 4;
            unsigned* db = &Bs[rb * BS_STRIDE + cb];
            float4 u = bReg[wch];
            db[0] = f2tf(u.x); db[1] = f2tf(u.y);
            db[2] = f2tf(u.z); db[3] = f2tf(u.w);
        }
    };

    const int KT = D / BK;
    loadTile(0);

    for (int kt = 0; kt < KT; kt++) {
        storeTile();
        __syncthreads();
        if (kt + 1 < KT) loadTile(kt + 1);

#pragma unroll
        for (int ks = 0; ks < 2; ks++) {
            const int k0 = ks * 8;
            unsigned af[4][4], bf[4][2];
            const int kk = k0 + (lane & 3);
#pragma unroll
            for (int i = 0; i < 4; i++) {
                int r = warpRow + i * 16 + (lane >> 2);
                af[i][0] = As[r * AS_STRIDE + kk];
                af[i][1] = As[(r + 8) * AS_STRIDE + kk];
                af[i][2] = As[r * AS_STRIDE + kk + 4];
                af[i][3] = As[(r + 8) * AS_STRIDE + kk + 4];
            }
#pragma unroll
            for (int j = 0; j < 4; j++) {
                int col = warpCol + j * 8 + (lane >> 2);
                bf[j][0] = Bs[kk * BS_STRIDE + col];
                bf[j][1] = Bs[(kk + 4) * BS_STRIDE + col];
            }
#pragma unroll
            for (int i = 0; i < 4; i++)
#pragma unroll
                for (int j = 0; j < 4; j++) {
                    asm volatile(
                        "mma.sync.aligned.m16n8k8.row.col.f32.tf32.tf32.f32 "
                        "{%0,%1,%2,%3}, {%4,%5,%6,%7}, {%8,%9}, {%0,%1,%2,%3};"
                        : "+f"(c[i][j][0]), "+f"(c[i][j][1]),
                          "+f"(c[i][j][2]), "+f"(c[i][j][3])
                        : "r"(af[i][0]), "r"(af[i][1]),
                          "r"(af[i][2]), "r"(af[i][3]),
                          "r"(bf[j][0]), "r"(bf[j][1]));
                }
        }
        __syncthreads();
    }

#pragma unroll
    for (int i = 0; i < 4; i++) {
        int r0 = blockRow + warpRow + i * 16 + (lane >> 2);
        int r1 = r0 + 8;
#pragma unroll
        for (int j = 0; j < 4; j++) {
            int col = blockCol + warpCol + j * 8 + (lane & 3) * 2;
            if (r0 < M) {
                float2 v;
                v.x = fmaxf(c[i][j][0], 0.f);
                v.y = fmaxf(c[i][j][1], 0.f);
                *reinterpret_cast<float2*>(out + (size_t)r0 * D + col) = v;
            }
            if (r1 < M) {
                float2 v;
                v.x = fmaxf(c[i][j][2], 0.f);
                v.y = fmaxf(c[i][j][3], 0.f);
                *reinterpret_cast<float2*>(out + (size_t)r1 * D + col) = v;
            }
        }
    }
}

// ---------------------------------------------------------------------------
// kernel_launch
// ---------------------------------------------------------------------------
extern "C" void kernel_launch(void* const* d_in, const int* in_sizes, int n_in,
                              void* d_out, int out_size) {
    const float* h  = (const float*)d_in[0];
    const float* Wt = (const float*)d_in[1];
    const float* ew = (const float*)d_in[2];
    const void* src = d_in[3];
    const void* dst = d_in[4];
    float* out = (float*)d_out;

    int M = in_sizes[0] / D;
    int E = in_sizes[2];

    detect_idx_dtype<<<1, 1>>>((const unsigned*)src);
    zero_cnt<<<(M + 255) / 256, 256>>>(M);
    hist_dst<<<(E + 255) / 256, 256>>>(dst, E);

    int sblocks = (M + SCAN_TILE - 1) / SCAN_TILE;
    scan_phase1<<<sblocks, SCAN_TILE>>>(M);
    scan_phase2<<<1, 32>>>(sblocks);
    scan_phase3<<<sblocks, SCAN_TILE>>>(M, E);

    reorder_edges<<<(E + 255) / 256, 256>>>(src, dst, ew, E);

    long long gthreads = (long long)M * 32;
    gather_agg<<<(int)((gthreads + 255) / 256), 256>>>(h, M);

    dim3 grid(D / BN, (M + BM - 1) / BM);
    gemm_relu<<<grid, 256>>>(Wt, out, M);
}

// round 5
// speedup vs baseline: 1.9075x; 1.0273x over previous
#include <cuda_runtime.h>
#include <cstdint>

#define D 512
#define MAX_NODES 100000
#define MAX_E 2000000
#define SCAN_TILE 1024
#define MAX_SCAN_BLOCKS 128

// Scratch: agg[n] = sum_e w_e * h[src_e]  (fp32, D_IN space)
__device__ float g_agg[(size_t)MAX_NODES * D];
__device__ int g_is64;
// CSR-by-dst structures
__device__ int   g_cnt[MAX_NODES];
__device__ int   g_off[MAX_NODES + 1];
__device__ int   g_cur[MAX_NODES];
__device__ int   g_srcs[MAX_E];
__device__ float g_ws[MAX_E];
__device__ int   g_bsum[MAX_SCAN_BLOCKS];

// ---------------------------------------------------------------------------
__global__ void detect_idx_dtype(const unsigned* __restrict__ src_words) {
    int all_zero = 1;
    for (int i = 1; i < 64; i += 2)
        if (src_words[i] != 0u) all_zero = 0;
    g_is64 = all_zero;
}

__global__ void zero_cnt(int M) {
    int i = blockIdx.x * blockDim.x + threadIdx.x;
    if (i < M) g_cnt[i] = 0;
}

__global__ void hist_dst(const void* __restrict__ dst_raw, int E) {
    int e = blockIdx.x * blockDim.x + threadIdx.x;
    if (e >= E) return;
    int d = g_is64 ? (int)reinterpret_cast<const long long*>(dst_raw)[e]
                   : reinterpret_cast<const int*>(dst_raw)[e];
    atomicAdd(&g_cnt[d], 1);
}

// ---------------------------------------------------------------------------
// Multi-block exclusive scan
// ---------------------------------------------------------------------------
__global__ void scan_phase1(int M) {
    __shared__ int wsum[32];
    const int tid = threadIdx.x, lane = tid & 31, wid = tid >> 5;
    const int gi = blockIdx.x * SCAN_TILE + tid;

    int x = (gi < M) ? g_cnt[gi] : 0;

    int v = x;
#pragma unroll
    for (int d = 1; d < 32; d <<= 1) {
        int t = __shfl_up_sync(0xffffffffu, v, d);
        if (lane >= d) v += t;
    }
    if (lane == 31) wsum[wid] = v;
    __syncthreads();
    if (wid == 0) {
        int w = wsum[lane];
#pragma unroll
        for (int d = 1; d < 32; d <<= 1) {
            int t = __shfl_up_sync(0xffffffffu, w, d);
            if (lane >= d) w += t;
        }
        wsum[lane] = w;
    }
    __syncthreads();

    int excl = (v - x) + (wid > 0 ? wsum[wid - 1] : 0);
    if (gi < M) g_off[gi] = excl;
    if (tid == SCAN_TILE - 1) g_bsum[blockIdx.x] = excl + x;
}

__global__ void scan_phase2(int nblocks) {
    const int lane = threadIdx.x;
    int run = 0;
    for (int base = 0; base < nblocks; base += 32) {
        int i = base + lane;
        int x = (i < nblocks) ? g_bsum[i] : 0;
        int v = x;
#pragma unroll
        for (int d = 1; d < 32; d <<= 1) {
            int t = __shfl_up_sync(0xffffffffu, v, d);
            if (lane >= d) v += t;
        }
        if (i < nblocks) g_bsum[i] = run + (v - x);
        run += __shfl_sync(0xffffffffu, v, 31);
    }
}

__global__ void scan_phase3(int M, int E) {
    const int gi = blockIdx.x * SCAN_TILE + threadIdx.x;
    if (gi < M) {
        int o = g_off[gi] + g_bsum[blockIdx.x];
        g_off[gi] = o;
        g_cur[gi] = o;
    }
    if (gi == 0) g_off[M] = E;
}

// ---------------------------------------------------------------------------
__global__ void reorder_edges(const void* __restrict__ src_raw,
                              const void* __restrict__ dst_raw,
                              const float* __restrict__ ew, int E) {
    int e = blockIdx.x * blockDim.x + threadIdx.x;
    if (e >= E) return;
    int s, d;
    if (g_is64) {
        s = (int)reinterpret_cast<const long long*>(src_raw)[e];
        d = (int)reinterpret_cast<const long long*>(dst_raw)[e];
    } else {
        s = reinterpret_cast<const int*>(src_raw)[e];
        d = reinterpret_cast<const int*>(dst_raw)[e];
    }
    int pos = atomicAdd(&g_cur[d], 1);
    g_srcs[pos] = s;
    g_ws[pos] = ew[e];
}

// ---------------------------------------------------------------------------
// Gather: one warp per dst node (unchanged)
// ---------------------------------------------------------------------------
__global__ void gather_agg(const float* __restrict__ h, int M) {
    int node = (int)((blockIdx.x * (unsigned)blockDim.x + threadIdx.x) >> 5);
    if (node >= M) return;
    const int lane = threadIdx.x & 31;
    const int beg = g_off[node];
    const int end = g_off[node + 1];

    float4 a0 = make_float4(0.f, 0.f, 0.f, 0.f), a1 = a0, a2 = a0, a3 = a0;

    int e = beg;
    for (; e + 1 < end; e += 2) {
        int s0 = g_srcs[e], s1 = g_srcs[e + 1];
        float w0 = g_ws[e], w1 = g_ws[e + 1];
        const float4* p0 = reinterpret_cast<const float4*>(h + (size_t)s0 * D);
        const float4* p1 = reinterpret_cast<const float4*>(h + (size_t)s1 * D);
        float4 v00 = p0[lane], v01 = p0[lane + 32],
               v02 = p0[lane + 64], v03 = p0[lane + 96];
        float4 v10 = p1[lane], v11 = p1[lane + 32],
               v12 = p1[lane + 64], v13 = p1[lane + 96];
        a0.x += v00.x * w0; a0.y += v00.y * w0; a0.z += v00.z * w0; a0.w += v00.w * w0;
        a1.x += v01.x * w0; a1.y += v01.y * w0; a1.z += v01.z * w0; a1.w += v01.w * w0;
        a2.x += v02.x * w0; a2.y += v02.y * w0; a2.z += v02.z * w0; a2.w += v02.w * w0;
        a3.x += v03.x * w0; a3.y += v03.y * w0; a3.z += v03.z * w0; a3.w += v03.w * w0;
        a0.x += v10.x * w1; a0.y += v10.y * w1; a0.z += v10.z * w1; a0.w += v10.w * w1;
        a1.x += v11.x * w1; a1.y += v11.y * w1; a1.z += v11.z * w1; a1.w += v11.w * w1;
        a2.x += v12.x * w1; a2.y += v12.y * w1; a2.z += v12.z * w1; a2.w += v12.w * w1;
        a3.x += v13.x * w1; a3.y += v13.y * w1; a3.z += v13.z * w1; a3.w += v13.w * w1;
    }
    if (e < end) {
        int s0 = g_srcs[e];
        float w0 = g_ws[e];
        const float4* p0 = reinterpret_cast<const float4*>(h + (size_t)s0 * D);
        float4 v00 = p0[lane], v01 = p0[lane + 32],
               v02 = p0[lane + 64], v03 = p0[lane + 96];
        a0.x += v00.x * w0; a0.y += v00.y * w0; a0.z += v00.z * w0; a0.w += v00.w * w0;
        a1.x += v01.x * w0; a1.y += v01.y * w0; a1.z += v01.z * w0; a1.w += v01.w * w0;
        a2.x += v02.x * w0; a2.y += v02.y * w0; a2.z += v02.z * w0; a2.w += v02.w * w0;
        a3.x += v03.x * w0; a3.y += v03.y * w0; a3.z += v03.z * w0; a3.w += v03.w * w0;
    }

    float4* o = reinterpret_cast<float4*>(g_agg + (size_t)node * D);
    o[lane] = a0; o[lane + 32] = a1; o[lane + 64] = a2; o[lane + 96] = a3;
}

// ---------------------------------------------------------------------------
// tf32 mma.sync GEMM:  out = relu( g_agg[M,512] @ W[512,512] )
// Block tile 128x256, BK=16, 256 threads (8 warps as 2(M) x 4(N)),
// warp tile 64x64 -> LDS-words per MMA = 1.0 (was 1.5) => tensor-bound.
// ---------------------------------------------------------------------------
#define BM 128
#define BN 256
#define BK 16
#define AS_STRIDE 20   // 16 + 4 pad, conflict-free
#define BS_STRIDE 264  // 256 + 8 pad: 264 % 32 == 8 -> conflict-free frag reads

__device__ __forceinline__ unsigned f2tf(float x) {
    unsigned u;
    asm("cvt.rna.tf32.f32 %0, %1;" : "=r"(u) : "f"(x));
    return u;
}

__global__ __launch_bounds__(256, 1)
void gemm_relu(const float* __restrict__ Bmat, float* __restrict__ out, int M) {
    __shared__ unsigned As[BM * AS_STRIDE];   // 10 KB
    __shared__ unsigned Bs[BK * BS_STRIDE];   // 16.5 KB

    const int tid  = threadIdx.x;
    const int warp = tid >> 5;
    const int lane = tid & 31;
    const int wm = warp & 1;          // 2 warps along M
    const int wn = warp >> 1;         // 4 warps along N
    const int warpRow = wm * 64;
    const int warpCol = wn * 64;
    const int blockRow = blockIdx.y * BM;
    const int blockCol = blockIdx.x * BN;
    const float* A = g_agg;

    float c[4][8][4];
#pragma unroll
    for (int i = 0; i < 4; i++)
#pragma unroll
        for (int j = 0; j < 8; j++)
#pragma unroll
            for (int q = 0; q < 4; q++) c[i][j][q] = 0.f;

    float4 aReg[2], bReg[4];

    // A tile: 128x16 = 512 float4 (2 per thread); B tile: 16x256 = 1024 float4 (4/thread)
    auto loadTile = [&](int kt) {
#pragma unroll
        for (int wch = 0; wch < 2; wch++) {
            int idx = tid + wch * 256;
            int ra = idx >> 2, ca = (idx & 3) * 4;
            int grow = blockRow + ra;
            if (grow < M)
                aReg[wch] = *reinterpret_cast<const float4*>(
                    A + (size_t)grow * D + kt * BK + ca);
            else
                aReg[wch] = make_float4(0.f, 0.f, 0.f, 0.f);
        }
#pragma unroll
        for (int wch = 0; wch < 4; wch++) {
            int idx = tid + wch * 256;
            int rb = idx >> 6, cb = (idx & 63) * 4;
            bReg[wch] = *reinterpret_cast<const float4*>(
                Bmat + (size_t)(kt * BK + rb) * D + blockCol + cb);
        }
    };
    auto storeTile = [&]() {
#pragma unroll
        for (int wch = 0; wch < 2; wch++) {
            int idx = tid + wch * 256;
            int ra = idx >> 2, ca = (idx & 3) * 4;
            unsigned* da = &As[ra * AS_STRIDE + ca];
            float4 v = aReg[wch];
            da[0] = f2tf(v.x); da[1] = f2tf(v.y);
            da[2] = f2tf(v.z); da[3] = f2tf(v.w);
        }
#pragma unroll
        for (int wch = 0; wch < 4; wch++) {
            int idx = tid + wch * 256;
            int rb = idx >> 6, cb = (idx & 63) * 4;
            unsigned* db = &Bs[rb * BS_STRIDE + cb];
            float4 u = bReg[wch];
            db[0] = f2tf(u.x); db[1] = f2tf(u.y);
            db[2] = f2tf(u.z); db[3] = f2tf(u.w);
        }
    };

    const int KT = D / BK;  // 32
    loadTile(0);

    for (int kt = 0; kt < KT; kt++) {
        storeTile();
        __syncthreads();
        if (kt + 1 < KT) loadTile(kt + 1);  // prefetch next tile into regs

#pragma unroll
        for (int ks = 0; ks < 2; ks++) {
            const int k0 = ks * 8;
            unsigned af[4][4], bf[8][2];
            const int kk = k0 + (lane & 3);
#pragma unroll
            for (int i = 0; i < 4; i++) {
                int r = warpRow + i * 16 + (lane >> 2);
                af[i][0] = As[r * AS_STRIDE + kk];
                af[i][1] = As[(r + 8) * AS_STRIDE + kk];
                af[i][2] = As[r * AS_STRIDE + kk + 4];
                af[i][3] = As[(r + 8) * AS_STRIDE + kk + 4];
            }
#pragma unroll
            for (int j = 0; j < 8; j++) {
                int col = warpCol + j * 8 + (lane >> 2);
                bf[j][0] = Bs[kk * BS_STRIDE + col];
                bf[j][1] = Bs[(kk + 4) * BS_STRIDE + col];
            }
#pragma unroll
            for (int i = 0; i < 4; i++)
#pragma unroll
                for (int j = 0; j < 8; j++) {
                    asm volatile(
                        "mma.sync.aligned.m16n8k8.row.col.f32.tf32.tf32.f32 "
                        "{%0,%1,%2,%3}, {%4,%5,%6,%7}, {%8,%9}, {%0,%1,%2,%3};"
                        : "+f"(c[i][j][0]), "+f"(c[i][j][1]),
                          "+f"(c[i][j][2]), "+f"(c[i][j][3])
                        : "r"(af[i][0]), "r"(af[i][1]),
                          "r"(af[i][2]), "r"(af[i][3]),
                          "r"(bf[j][0]), "r"(bf[j][1]));
                }
        }
        __syncthreads();
    }

    // Epilogue: ReLU + store
#pragma unroll
    for (int i = 0; i < 4; i++) {
        int r0 = blockRow + warpRow + i * 16 + (lane >> 2);
        int r1 = r0 + 8;
#pragma unroll
        for (int j = 0; j < 8; j++) {
            int col = blockCol + warpCol + j * 8 + (lane & 3) * 2;
            if (r0 < M) {
                float2 v;
                v.x = fmaxf(c[i][j][0], 0.f);
                v.y = fmaxf(c[i][j][1], 0.f);
                *reinterpret_cast<float2*>(out + (size_t)r0 * D + col) = v;
            }
            if (r1 < M) {
                float2 v;
                v.x = fmaxf(c[i][j][2], 0.f);
                v.y = fmaxf(c[i][j][3], 0.f);
                *reinterpret_cast<float2*>(out + (size_t)r1 * D + col) = v;
            }
        }
    }
}

// ---------------------------------------------------------------------------
// kernel_launch
// ---------------------------------------------------------------------------
extern "C" void kernel_launch(void* const* d_in, const int* in_sizes, int n_in,
                              void* d_out, int out_size) {
    const float* h  = (const float*)d_in[0];
    const float* Wt = (const float*)d_in[1];
    const float* ew = (const float*)d_in[2];
    const void* src = d_in[3];
    const void* dst = d_in[4];
    float* out = (float*)d_out;

    int M = in_sizes[0] / D;
    int E = in_sizes[2];

    detect_idx_dtype<<<1, 1>>>((const unsigned*)src);
    zero_cnt<<<(M + 255) / 256, 256>>>(M);
    hist_dst<<<(E + 255) / 256, 256>>>(dst, E);

    int sblocks = (M + SCAN_TILE - 1) / SCAN_TILE;
    scan_phase1<<<sblocks, SCAN_TILE>>>(M);
    scan_phase2<<<1, 32>>>(sblocks);
    scan_phase3<<<sblocks, SCAN_TILE>>>(M, E);

    reorder_edges<<<(E + 255) / 256, 256>>>(src, dst, ew, E);

    long long gthreads = (long long)M * 32;
    gather_agg<<<(int)((gthreads + 255) / 256), 256>>>(h, M);

    dim3 grid(D / BN, (M + BM - 1) / BM);
    gemm_relu<<<grid, 256>>>(Wt, out, M);
}

// round 8
// speedup vs baseline: 3.1631x; 1.6583x over previous
#include <cuda_runtime.h>
#include <cuda_fp16.h>
#include <cstdint>

#define D 512
#define ROW_U4 64         // uint4 per fp16 row (512*2B/16B)
#define MAX_NODES 100000
#define MAX_E 2000000
#define SCAN_TILE 1024
#define MAX_SCAN_BLOCKS 128

// fp16 copies (uint4-typed for alignment)
__device__ uint4 g_h2[(size_t)MAX_NODES * ROW_U4];     // h in fp16
__device__ uint4 g_agg_h[(size_t)MAX_NODES * ROW_U4];  // agg in fp16 (GEMM A)
__device__ uint4 g_wt_h[(size_t)D * D / 8];            // W^T fp16 [N][K]
__device__ int g_is64;
// CSR-by-dst structures
__device__ int   g_cnt[MAX_NODES];
__device__ int   g_off[MAX_NODES + 1];
__device__ int   g_cur[MAX_NODES];
__device__ int   g_srcs[MAX_E];
__device__ float g_ws[MAX_E];
__device__ int   g_bsum[MAX_SCAN_BLOCKS];

// Bit-cast helpers (the intrinsics I used before don't exist)
__device__ __forceinline__ unsigned h2_to_u(__half2 h) {
    return *reinterpret_cast<unsigned*>(&h);
}
__device__ __forceinline__ __half2 u_to_h2(unsigned u) {
    return *reinterpret_cast<__half2*>(&u);
}

// ---------------------------------------------------------------------------
__global__ void detect_idx_dtype(const unsigned* __restrict__ src_words) {
    int all_zero = 1;
    for (int i = 1; i < 64; i += 2)
        if (src_words[i] != 0u) all_zero = 0;
    g_is64 = all_zero;
}

// Convert h (fp32) -> g_h2 (fp16). One uint4 (8 halves) per thread-iter.
__global__ void convert_h(const float* __restrict__ h, long long n_u4) {
    long long i = blockIdx.x * (long long)blockDim.x + threadIdx.x;
    long long stride = gridDim.x * (long long)blockDim.x;
    for (; i < n_u4; i += stride) {
        const float4* p = reinterpret_cast<const float4*>(h + i * 8);
        float4 v0 = p[0], v1 = p[1];
        uint4 o;
        o.x = h2_to_u(__floats2half2_rn(v0.x, v0.y));
        o.y = h2_to_u(__floats2half2_rn(v0.z, v0.w));
        o.z = h2_to_u(__floats2half2_rn(v1.x, v1.y));
        o.w = h2_to_u(__floats2half2_rn(v1.z, v1.w));
        g_h2[i] = o;
    }
}

// Transpose W [K][N] fp32 -> g_wt_h [N][K] fp16.
__global__ void transpose_w_h(const float* __restrict__ W) {
    __shared__ float t[32][33];
    int bx = blockIdx.x * 32, by = blockIdx.y * 32;
    t[threadIdx.y][threadIdx.x] = W[(by + threadIdx.y) * D + bx + threadIdx.x];
    __syncthreads();
    __half* wt = reinterpret_cast<__half*>(g_wt_h);
    wt[(size_t)(bx + threadIdx.y) * D + by + threadIdx.x] =
        __float2half_rn(t[threadIdx.x][threadIdx.y]);
}

__global__ void zero_cnt(int M) {
    int i = blockIdx.x * blockDim.x + threadIdx.x;
    if (i < M) g_cnt[i] = 0;
}

__global__ void hist_dst(const void* __restrict__ dst_raw, int E) {
    int e = blockIdx.x * blockDim.x + threadIdx.x;
    if (e >= E) return;
    int d = g_is64 ? (int)reinterpret_cast<const long long*>(dst_raw)[e]
                   : reinterpret_cast<const int*>(dst_raw)[e];
    atomicAdd(&g_cnt[d], 1);
}

__global__ void scan_phase1(int M) {
    __shared__ int wsum[32];
    const int tid = threadIdx.x, lane = tid & 31, wid = tid >> 5;
    const int gi = blockIdx.x * SCAN_TILE + tid;

    int x = (gi < M) ? g_cnt[gi] : 0;

    int v = x;
#pragma unroll
    for (int d = 1; d < 32; d <<= 1) {
        int t = __shfl_up_sync(0xffffffffu, v, d);
        if (lane >= d) v += t;
    }
    if (lane == 31) wsum[wid] = v;
    __syncthreads();
    if (wid == 0) {
        int w = wsum[lane];
#pragma unroll
        for (int d = 1; d < 32; d <<= 1) {
            int t = __shfl_up_sync(0xffffffffu, w, d);
            if (lane >= d) w += t;
        }
        wsum[lane] = w;
    }
    __syncthreads();

    int excl = (v - x) + (wid > 0 ? wsum[wid - 1] : 0);
    if (gi < M) g_off[gi] = excl;
    if (tid == SCAN_TILE - 1) g_bsum[blockIdx.x] = excl + x;
}

__global__ void scan_phase2(int nblocks) {
    const int lane = threadIdx.x;
    int run = 0;
    for (int base = 0; base < nblocks; base += 32) {
        int i = base + lane;
        int x = (i < nblocks) ? g_bsum[i] : 0;
        int v = x;
#pragma unroll
        for (int d = 1; d < 32; d <<= 1) {
            int t = __shfl_up_sync(0xffffffffu, v, d);
            if (lane >= d) v += t;
        }
        if (i < nblocks) g_bsum[i] = run + (v - x);
        run += __shfl_sync(0xffffffffu, v, 31);
    }
}

__global__ void scan_phase3(int M, int E) {
    const int gi = blockIdx.x * SCAN_TILE + threadIdx.x;
    if (gi < M) {
        int o = g_off[gi] + g_bsum[blockIdx.x];
        g_off[gi] = o;
        g_cur[gi] = o;
    }
    if (gi == 0) g_off[M] = E;
}

__global__ void reorder_edges(const void* __restrict__ src_raw,
                              const void* __restrict__ dst_raw,
                              const float* __restrict__ ew, int E) {
    int e = blockIdx.x * blockDim.x + threadIdx.x;
    if (e >= E) return;
    int s, d;
    if (g_is64) {
        s = (int)reinterpret_cast<const long long*>(src_raw)[e];
        d = (int)reinterpret_cast<const long long*>(dst_raw)[e];
    } else {
        s = reinterpret_cast<const int*>(src_raw)[e];
        d = reinterpret_cast<const int*>(dst_raw)[e];
    }
    int pos = atomicAdd(&g_cur[d], 1);
    g_srcs[pos] = s;
    g_ws[pos] = ew[e];
}

// ---------------------------------------------------------------------------
// Gather (fp16 rows): one warp per dst node. Per lane: 2 uint4 = 16 halves.
// fp32 accumulation, fp16 output row (GEMM A).
// ---------------------------------------------------------------------------
__device__ __forceinline__ void acc_u4(float2* acc, uint4 q, float w, int base) {
    float2 f;
    f = __half22float2(u_to_h2(q.x));
    acc[base + 0].x += f.x * w; acc[base + 0].y += f.y * w;
    f = __half22float2(u_to_h2(q.y));
    acc[base + 1].x += f.x * w; acc[base + 1].y += f.y * w;
    f = __half22float2(u_to_h2(q.z));
    acc[base + 2].x += f.x * w; acc[base + 2].y += f.y * w;
    f = __half22float2(u_to_h2(q.w));
    acc[base + 3].x += f.x * w; acc[base + 3].y += f.y * w;
}

__global__ void gather_agg(int M) {
    int node = (int)((blockIdx.x * (unsigned)blockDim.x + threadIdx.x) >> 5);
    if (node >= M) return;
    const int lane = threadIdx.x & 31;
    const int beg = g_off[node];
    const int end = g_off[node + 1];

    float2 acc[8];
#pragma unroll
    for (int i = 0; i < 8; i++) acc[i] = make_float2(0.f, 0.f);

    int e = beg;
    for (; e + 1 < end; e += 2) {
        int s0 = g_srcs[e], s1 = g_srcs[e + 1];
        float w0 = g_ws[e], w1 = g_ws[e + 1];
        const uint4* p0 = g_h2 + (size_t)s0 * ROW_U4 + lane * 2;
        const uint4* p1 = g_h2 + (size_t)s1 * ROW_U4 + lane * 2;
        uint4 q00 = p0[0], q01 = p0[1];
        uint4 q10 = p1[0], q11 = p1[1];
        acc_u4(acc, q00, w0, 0); acc_u4(acc, q01, w0, 4);
        acc_u4(acc, q10, w1, 0); acc_u4(acc, q11, w1, 4);
    }
    if (e < end) {
        int s0 = g_srcs[e];
        float w0 = g_ws[e];
        const uint4* p0 = g_h2 + (size_t)s0 * ROW_U4 + lane * 2;
        uint4 q00 = p0[0], q01 = p0[1];
        acc_u4(acc, q00, w0, 0); acc_u4(acc, q01, w0, 4);
    }

    uint4 o0, o1;
    o0.x = h2_to_u(__floats2half2_rn(acc[0].x, acc[0].y));
    o0.y = h2_to_u(__floats2half2_rn(acc[1].x, acc[1].y));
    o0.z = h2_to_u(__floats2half2_rn(acc[2].x, acc[2].y));
    o0.w = h2_to_u(__floats2half2_rn(acc[3].x, acc[3].y));
    o1.x = h2_to_u(__floats2half2_rn(acc[4].x, acc[4].y));
    o1.y = h2_to_u(__floats2half2_rn(acc[5].x, acc[5].y));
    o1.z = h2_to_u(__floats2half2_rn(acc[6].x, acc[6].y));
    o1.w = h2_to_u(__floats2half2_rn(acc[7].x, acc[7].y));
    uint4* o = g_agg_h + (size_t)node * ROW_U4 + lane * 2;
    o[0] = o0; o[1] = o1;
}

// ---------------------------------------------------------------------------
// fp16 mma.sync GEMM:  out = relu( agg_h[M,512] @ W )  with W^T fp16 [N][K].
// Block tile 128x256, BK=32, 256 threads (8 warps as 2(M) x 4(N)),
// warp tile 64x64, mma m16n8k16 (2x MACs/instr vs tf32 k8).
// smem layout in half2 units, row stride 20 (16 + 4 pad) -> conflict-free.
// ---------------------------------------------------------------------------
#define BM 128
#define BN 256
#define BK 32
#define HS 20   // half2 stride per row

__global__ __launch_bounds__(256, 1)
void gemm_relu(float* __restrict__ out, int M) {
    __shared__ unsigned As[BM * HS];   // half2 units, 10 KB
    __shared__ unsigned Bs[BN * HS];   // 20 KB

    const int tid  = threadIdx.x;
    const int warp = tid >> 5;
    const int lane = tid & 31;
    const int wm = warp & 1;          // 2 warps along M
    const int wn = warp >> 1;         // 4 warps along N
    const int warpRow = wm * 64;
    const int warpCol = wn * 64;
    const int blockRow = blockIdx.y * BM;
    const int blockCol = blockIdx.x * BN;

    float c[4][8][4];
#pragma unroll
    for (int i = 0; i < 4; i++)
#pragma unroll
        for (int j = 0; j < 8; j++)
#pragma unroll
            for (int q = 0; q < 4; q++) c[i][j][q] = 0.f;

    uint4 aReg[2], bReg[4];

    // A tile: 128 rows x 32 halves = 512 uint4 (2/thread).
    // B tile: 256 rows x 32 halves = 1024 uint4 (4/thread).
    auto loadTile = [&](int kt) {
#pragma unroll
        for (int wch = 0; wch < 2; wch++) {
            int idx = tid + wch * 256;
            int ra = idx >> 2, ca = idx & 3;
            int grow = blockRow + ra;
            if (grow < M)
                aReg[wch] = g_agg_h[(size_t)grow * ROW_U4 + kt * 4 + ca];
            else
                aReg[wch] = make_uint4(0u, 0u, 0u, 0u);
        }
#pragma unroll
        for (int wch = 0; wch < 4; wch++) {
            int idx = tid + wch * 256;
            int rb = idx >> 2, cb = idx & 3;
            bReg[wch] = g_wt_h[(size_t)(blockCol + rb) * (D / 8) + kt * 4 + cb];
        }
    };
    auto storeTile = [&]() {
#pragma unroll
        for (int wch = 0; wch < 2; wch++) {
            int idx = tid + wch * 256;
            int ra = idx >> 2, ca = idx & 3;
            unsigned* da = &As[ra * HS + ca * 4];
            uint4 v = aReg[wch];
            da[0] = v.x; da[1] = v.y; da[2] = v.z; da[3] = v.w;
        }
#pragma unroll
        for (int wch = 0; wch < 4; wch++) {
            int idx = tid + wch * 256;
            int rb = idx >> 2, cb = idx & 3;
            unsigned* db = &Bs[rb * HS + cb * 4];
            uint4 u = bReg[wch];
            db[0] = u.x; db[1] = u.y; db[2] = u.z; db[3] = u.w;
        }
    };

    const int KT = D / BK;  // 16
    loadTile(0);

    for (int kt = 0; kt < KT; kt++) {
        storeTile();
        __syncthreads();
        if (kt + 1 < KT) loadTile(kt + 1);  // prefetch next tile into regs

#pragma unroll
        for (int ks = 0; ks < 2; ks++) {     // two k16 steps per BK=32
            const int kb = ks * 8;           // half2 base
            unsigned af[4][4], bf[8][2];
            const int cc = kb + (lane & 3);
#pragma unroll
            for (int i = 0; i < 4; i++) {
                int r = warpRow + i * 16 + (lane >> 2);
                af[i][0] = As[r * HS + cc];
                af[i][1] = As[(r + 8) * HS + cc];
                af[i][2] = As[r * HS + cc + 4];
                af[i][3] = As[(r + 8) * HS + cc + 4];
            }
#pragma unroll
            for (int j = 0; j < 8; j++) {
                int n = warpCol + j * 8 + (lane >> 2);
                bf[j][0] = Bs[n * HS + cc];
                bf[j][1] = Bs[n * HS + cc + 4];
            }
#pragma unroll
            for (int i = 0; i < 4; i++)
#pragma unroll
                for (int j = 0; j < 8; j++) {
                    asm volatile(
                        "mma.sync.aligned.m16n8k16.row.col.f32.f16.f16.f32 "
                        "{%0,%1,%2,%3}, {%4,%5,%6,%7}, {%8,%9}, {%0,%1,%2,%3};"
                        : "+f"(c[i][j][0]), "+f"(c[i][j][1]),
                          "+f"(c[i][j][2]), "+f"(c[i][j][3])
                        : "r"(af[i][0]), "r"(af[i][1]),
                          "r"(af[i][2]), "r"(af[i][3]),
                          "r"(bf[j][0]), "r"(bf[j][1]));
                }
        }
        __syncthreads();
    }

    // Epilogue: ReLU + store
#pragma unroll
    for (int i = 0; i < 4; i++) {
        int r0 = blockRow + warpRow + i * 16 + (lane >> 2);
        int r1 = r0 + 8;
#pragma unroll
        for (int j = 0; j < 8; j++) {
            int col = blockCol + warpCol + j * 8 + (lane & 3) * 2;
            if (r0 < M) {
                float2 v;
                v.x = fmaxf(c[i][j][0], 0.f);
                v.y = fmaxf(c[i][j][1], 0.f);
                *reinterpret_cast<float2*>(out + (size_t)r0 * D + col) = v;
            }
            if (r1 < M) {
                float2 v;
                v.x = fmaxf(c[i][j][2], 0.f);
                v.y = fmaxf(c[i][j][3], 0.f);
                *reinterpret_cast<float2*>(out + (size_t)r1 * D + col) = v;
            }
        }
    }
}

// ---------------------------------------------------------------------------
// kernel_launch
// ---------------------------------------------------------------------------
extern "C" void kernel_launch(void* const* d_in, const int* in_sizes, int n_in,
                              void* d_out, int out_size) {
    const float* h  = (const float*)d_in[0];
    const float* Wt = (const float*)d_in[1];
    const float* ew = (const float*)d_in[2];
    const void* src = d_in[3];
    const void* dst = d_in[4];
    float* out = (float*)d_out;

    int M = in_sizes[0] / D;
    int E = in_sizes[2];

    detect_idx_dtype<<<1, 1>>>((const unsigned*)src);
    convert_h<<<2048, 256>>>(h, (long long)M * ROW_U4);
    transpose_w_h<<<dim3(16, 16), dim3(32, 32)>>>(Wt);
    zero_cnt<<<(M + 255) / 256, 256>>>(M);
    hist_dst<<<(E + 255) / 256, 256>>>(dst, E);

    int sblocks = (M + SCAN_TILE - 1) / SCAN_TILE;
    scan_phase1<<<sblocks, SCAN_TILE>>>(M);
    scan_phase2<<<1, 32>>>(sblocks);
    scan_phase3<<<sblocks, SCAN_TILE>>>(M, E);

    reorder_edges<<<(E + 255) / 256, 256>>>(src, dst, ew, E);

    long long gthreads = (long long)M * 32;
    gather_agg<<<(int)((gthreads + 255) / 256), 256>>>(M);

    dim3 grid(D / BN, (M + BM - 1) / BM);
    gemm_relu<<<grid, 256>>>(out, M);
}

// round 9
// speedup vs baseline: 3.2346x; 1.0226x over previous
#include <cuda_runtime.h>
#include <cuda_fp16.h>
#include <cstdint>

#define D 512
#define ROW_U4 64         // uint4 per fp16 row (512*2B/16B)
#define MAX_NODES 100000
#define MAX_E 2000000
#define SCAN_TILE 1024
#define MAX_SCAN_BLOCKS 128

// fp16 copies (uint4-typed for alignment)
__device__ uint4 g_h2[(size_t)MAX_NODES * ROW_U4];     // h in fp16
__device__ uint4 g_agg_h[(size_t)MAX_NODES * ROW_U4];  // agg in fp16 (GEMM A)
__device__ uint4 g_wt_h[(size_t)D * D / 8];            // W^T fp16 [N][K]
__device__ int g_is64;
// CSR-by-dst structures
__device__ int   g_cnt[MAX_NODES];
__device__ int   g_off[MAX_NODES + 1];
__device__ int   g_cur[MAX_NODES];
__device__ int2  g_edge[MAX_E];   // (src, edge_weight bits) combined
__device__ int   g_bsum[MAX_SCAN_BLOCKS];

// Bit-cast helpers
__device__ __forceinline__ unsigned h2_to_u(__half2 h) {
    return *reinterpret_cast<unsigned*>(&h);
}
__device__ __forceinline__ __half2 u_to_h2(unsigned u) {
    return *reinterpret_cast<__half2*>(&u);
}
__device__ __forceinline__ void ldsm_x4(unsigned& r0, unsigned& r1,
                                        unsigned& r2, unsigned& r3,
                                        uint32_t addr) {
    asm volatile(
        "ldmatrix.sync.aligned.m8n8.x4.shared.b16 {%0,%1,%2,%3}, [%4];"
        : "=r"(r0), "=r"(r1), "=r"(r2), "=r"(r3) : "r"(addr));
}

// ---------------------------------------------------------------------------
__global__ void detect_idx_dtype(const unsigned* __restrict__ src_words) {
    int all_zero = 1;
    for (int i = 1; i < 64; i += 2)
        if (src_words[i] != 0u) all_zero = 0;
    g_is64 = all_zero;
}

// Convert h (fp32) -> g_h2 (fp16). One uint4 (8 halves) per thread-iter.
__global__ void convert_h(const float* __restrict__ h, long long n_u4) {
    long long i = blockIdx.x * (long long)blockDim.x + threadIdx.x;
    long long stride = gridDim.x * (long long)blockDim.x;
    for (; i < n_u4; i += stride) {
        const float4* p = reinterpret_cast<const float4*>(h + i * 8);
        float4 v0 = p[0], v1 = p[1];
        uint4 o;
        o.x = h2_to_u(__floats2half2_rn(v0.x, v0.y));
        o.y = h2_to_u(__floats2half2_rn(v0.z, v0.w));
        o.z = h2_to_u(__floats2half2_rn(v1.x, v1.y));
        o.w = h2_to_u(__floats2half2_rn(v1.z, v1.w));
        g_h2[i] = o;
    }
}

// Transpose W [K][N] fp32 -> g_wt_h [N][K] fp16.
__global__ void transpose_w_h(const float* __restrict__ W) {
    __shared__ float t[32][33];
    int bx = blockIdx.x * 32, by = blockIdx.y * 32;
    t[threadIdx.y][threadIdx.x] = W[(by + threadIdx.y) * D + bx + threadIdx.x];
    __syncthreads();
    __half* wt = reinterpret_cast<__half*>(g_wt_h);
    wt[(size_t)(bx + threadIdx.y) * D + by + threadIdx.x] =
        __float2half_rn(t[threadIdx.x][threadIdx.y]);
}

__global__ void zero_cnt(int M) {
    int i = blockIdx.x * blockDim.x + threadIdx.x;
    if (i < M) g_cnt[i] = 0;
}

__global__ void hist_dst(const void* __restrict__ dst_raw, int E) {
    int e = blockIdx.x * blockDim.x + threadIdx.x;
    if (e >= E) return;
    int d = g_is64 ? (int)reinterpret_cast<const long long*>(dst_raw)[e]
                   : reinterpret_cast<const int*>(dst_raw)[e];
    atomicAdd(&g_cnt[d], 1);
}

__global__ void scan_phase1(int M) {
    __shared__ int wsum[32];
    const int tid = threadIdx.x, lane = tid & 31, wid = tid >> 5;
    const int gi = blockIdx.x * SCAN_TILE + tid;

    int x = (gi < M) ? g_cnt[gi] : 0;

    int v = x;
#pragma unroll
    for (int d = 1; d < 32; d <<= 1) {
        int t = __shfl_up_sync(0xffffffffu, v, d);
        if (lane >= d) v += t;
    }
    if (lane == 31) wsum[wid] = v;
    __syncthreads();
    if (wid == 0) {
        int w = wsum[lane];
#pragma unroll
        for (int d = 1; d < 32; d <<= 1) {
            int t = __shfl_up_sync(0xffffffffu, w, d);
            if (lane >= d) w += t;
        }
        wsum[lane] = w;
    }
    __syncthreads();

    int excl = (v - x) + (wid > 0 ? wsum[wid - 1] : 0);
    if (gi < M) g_off[gi] = excl;
    if (tid == SCAN_TILE - 1) g_bsum[blockIdx.x] = excl + x;
}

__global__ void scan_phase2(int nblocks) {
    const int lane = threadIdx.x;
    int run = 0;
    for (int base = 0; base < nblocks; base += 32) {
        int i = base + lane;
        int x = (i < nblocks) ? g_bsum[i] : 0;
        int v = x;
#pragma unroll
        for (int d = 1; d < 32; d <<= 1) {
            int t = __shfl_up_sync(0xffffffffu, v, d);
            if (lane >= d) v += t;
        }
        if (i < nblocks) g_bsum[i] = run + (v - x);
        run += __shfl_sync(0xffffffffu, v, 31);
    }
}

__global__ void scan_phase3(int M, int E) {
    const int gi = blockIdx.x * SCAN_TILE + threadIdx.x;
    if (gi < M) {
        int o = g_off[gi] + g_bsum[blockIdx.x];
        g_off[gi] = o;
        g_cur[gi] = o;
    }
    if (gi == 0) g_off[M] = E;
}

__global__ void reorder_edges(const void* __restrict__ src_raw,
                              const void* __restrict__ dst_raw,
                              const float* __restrict__ ew, int E) {
    int e = blockIdx.x * blockDim.x + threadIdx.x;
    if (e >= E) return;
    int s, d;
    if (g_is64) {
        s = (int)reinterpret_cast<const long long*>(src_raw)[e];
        d = (int)reinterpret_cast<const long long*>(dst_raw)[e];
    } else {
        s = reinterpret_cast<const int*>(src_raw)[e];
        d = reinterpret_cast<const int*>(dst_raw)[e];
    }
    int pos = atomicAdd(&g_cur[d], 1);
    g_edge[pos] = make_int2(s, __float_as_int(ew[e]));
}

// ---------------------------------------------------------------------------
// Gather (fp16 rows): one warp per dst node. Per lane: 2 uint4 = 16 halves.
// fp32 accumulation, fp16 output row (GEMM A).
// ---------------------------------------------------------------------------
__device__ __forceinline__ void acc_u4(float2* acc, uint4 q, float w, int base) {
    float2 f;
    f = __half22float2(u_to_h2(q.x));
    acc[base + 0].x += f.x * w; acc[base + 0].y += f.y * w;
    f = __half22float2(u_to_h2(q.y));
    acc[base + 1].x += f.x * w; acc[base + 1].y += f.y * w;
    f = __half22float2(u_to_h2(q.z));
    acc[base + 2].x += f.x * w; acc[base + 2].y += f.y * w;
    f = __half22float2(u_to_h2(q.w));
    acc[base + 3].x += f.x * w; acc[base + 3].y += f.y * w;
}

__global__ void gather_agg(int M) {
    int node = (int)((blockIdx.x * (unsigned)blockDim.x + threadIdx.x) >> 5);
    if (node >= M) return;
    const int lane = threadIdx.x & 31;
    const int beg = g_off[node];
    const int end = g_off[node + 1];

    float2 acc[8];
#pragma unroll
    for (int i = 0; i < 8; i++) acc[i] = make_float2(0.f, 0.f);

    int e = beg;
    for (; e + 1 < end; e += 2) {
        int2 e0 = g_edge[e], e1 = g_edge[e + 1];
        float w0 = __int_as_float(e0.y), w1 = __int_as_float(e1.y);
        const uint4* p0 = g_h2 + (size_t)e0.x * ROW_U4 + lane * 2;
        const uint4* p1 = g_h2 + (size_t)e1.x * ROW_U4 + lane * 2;
        uint4 q00 = p0[0], q01 = p0[1];
        uint4 q10 = p1[0], q11 = p1[1];
        acc_u4(acc, q00, w0, 0); acc_u4(acc, q01, w0, 4);
        acc_u4(acc, q10, w1, 0); acc_u4(acc, q11, w1, 4);
    }
    if (e < end) {
        int2 e0 = g_edge[e];
        float w0 = __int_as_float(e0.y);
        const uint4* p0 = g_h2 + (size_t)e0.x * ROW_U4 + lane * 2;
        uint4 q00 = p0[0], q01 = p0[1];
        acc_u4(acc, q00, w0, 0); acc_u4(acc, q01, w0, 4);
    }

    uint4 o0, o1;
    o0.x = h2_to_u(__floats2half2_rn(acc[0].x, acc[0].y));
    o0.y = h2_to_u(__floats2half2_rn(acc[1].x, acc[1].y));
    o0.z = h2_to_u(__floats2half2_rn(acc[2].x, acc[2].y));
    o0.w = h2_to_u(__floats2half2_rn(acc[3].x, acc[3].y));
    o1.x = h2_to_u(__floats2half2_rn(acc[4].x, acc[4].y));
    o1.y = h2_to_u(__floats2half2_rn(acc[5].x, acc[5].y));
    o1.z = h2_to_u(__floats2half2_rn(acc[6].x, acc[6].y));
    o1.w = h2_to_u(__floats2half2_rn(acc[7].x, acc[7].y));
    uint4* o = g_agg_h + (size_t)node * ROW_U4 + lane * 2;
    o[0] = o0; o[1] = o1;
}

// ---------------------------------------------------------------------------
// fp16 mma.sync GEMM:  out = relu( agg_h[M,512] @ W )  with W^T fp16 [N][K].
// Block tile 128x256, BK=32, 256 threads (8 warps as 2(M) x 4(N)),
// warp tile 64x64, mma m16n8k16, fragments via ldmatrix.x4.
// ---------------------------------------------------------------------------
#define BM 128
#define BN 256
#define BK 32
#define HS 20   // half2 stride per row

__global__ __launch_bounds__(256, 1)
void gemm_relu(float* __restrict__ out, int M) {
    __shared__ unsigned As[BM * HS];   // 10 KB
    __shared__ unsigned Bs[BN * HS];   // 20 KB

    const int tid  = threadIdx.x;
    const int warp = tid >> 5;
    const int lane = tid & 31;
    const int wm = warp & 1;          // 2 warps along M
    const int wn = warp >> 1;         // 4 warps along N
    const int warpRow = wm * 64;
    const int warpCol = wn * 64;
    const int blockRow = blockIdx.y * BM;
    const int blockCol = blockIdx.x * BN;

    const uint32_t as_base = (uint32_t)__cvta_generic_to_shared(As);
    const uint32_t bs_base = (uint32_t)__cvta_generic_to_shared(Bs);

    float c[4][8][4];
#pragma unroll
    for (int i = 0; i < 4; i++)
#pragma unroll
        for (int j = 0; j < 8; j++)
#pragma unroll
            for (int q = 0; q < 4; q++) c[i][j][q] = 0.f;

    uint4 aReg[2], bReg[4];

    auto loadTile = [&](int kt) {
#pragma unroll
        for (int wch = 0; wch < 2; wch++) {
            int idx = tid + wch * 256;
            int ra = idx >> 2, ca = idx & 3;
            int grow = blockRow + ra;
            if (grow < M)
                aReg[wch] = g_agg_h[(size_t)grow * ROW_U4 + kt * 4 + ca];
            else
                aReg[wch] = make_uint4(0u, 0u, 0u, 0u);
        }
#pragma unroll
        for (int wch = 0; wch < 4; wch++) {
            int idx = tid + wch * 256;
            int rb = idx >> 2, cb = idx & 3;
            bReg[wch] = g_wt_h[(size_t)(blockCol + rb) * (D / 8) + kt * 4 + cb];
        }
    };
    auto storeTile = [&]() {
#pragma unroll
        for (int wch = 0; wch < 2; wch++) {
            int idx = tid + wch * 256;
            int ra = idx >> 2, ca = idx & 3;
            unsigned* da = &As[ra * HS + ca * 4];
            uint4 v = aReg[wch];
            da[0] = v.x; da[1] = v.y; da[2] = v.z; da[3] = v.w;
        }
#pragma unroll
        for (int wch = 0; wch < 4; wch++) {
            int idx = tid + wch * 256;
            int rb = idx >> 2, cb = idx & 3;
            unsigned* db = &Bs[rb * HS + cb * 4];
            uint4 u = bReg[wch];
            db[0] = u.x; db[1] = u.y; db[2] = u.z; db[3] = u.w;
        }
    };

    // ldmatrix address components (constant across kt)
    const int a_row16 = lane & 15;          // row within 16-row tile
    const int a_khi   = (lane >> 4) << 2;   // +4 half2 for k-half 1
    const int b_row8  = lane & 7;
    const int b_jhi   = lane >> 4;          // +1 j-group for matrices 2,3
    const int b_khi   = ((lane >> 3) & 1) << 2;

    const int KT = D / BK;  // 16
    loadTile(0);

    for (int kt = 0; kt < KT; kt++) {
        storeTile();
        __syncthreads();
        if (kt + 1 < KT) loadTile(kt + 1);  // prefetch next tile into regs

#pragma unroll
        for (int ks = 0; ks < 2; ks++) {     // two k16 steps per BK=32
            unsigned af[4][4], bf[8][2];
#pragma unroll
            for (int i = 0; i < 4; i++) {
                uint32_t addr = as_base +
                    (((warpRow + i * 16 + a_row16) * HS) + ks * 8 + a_khi) * 4u;
                ldsm_x4(af[i][0], af[i][1], af[i][2], af[i][3], addr);
            }
#pragma unroll
            for (int jj = 0; jj < 4; jj++) {
                int j = jj * 2;
                uint32_t addr = bs_base +
                    (((warpCol + (j + b_jhi) * 8 + b_row8) * HS) + ks * 8 + b_khi) * 4u;
                ldsm_x4(bf[j][0], bf[j][1], bf[j + 1][0], bf[j + 1][1], addr);
            }
#pragma unroll
            for (int i = 0; i < 4; i++)
#pragma unroll
                for (int j = 0; j < 8; j++) {
                    asm volatile(
                        "mma.sync.aligned.m16n8k16.row.col.f32.f16.f16.f32 "
                        "{%0,%1,%2,%3}, {%4,%5,%6,%7}, {%8,%9}, {%0,%1,%2,%3};"
                        : "+f"(c[i][j][0]), "+f"(c[i][j][1]),
                          "+f"(c[i][j][2]), "+f"(c[i][j][3])
                        : "r"(af[i][0]), "r"(af[i][1]),
                          "r"(af[i][2]), "r"(af[i][3]),
                          "r"(bf[j][0]), "r"(bf[j][1]));
                }
        }
        __syncthreads();
    }

    // Epilogue: ReLU + store
#pragma unroll
    for (int i = 0; i < 4; i++) {
        int r0 = blockRow + warpRow + i * 16 + (lane >> 2);
        int r1 = r0 + 8;
#pragma unroll
        for (int j = 0; j < 8; j++) {
            int col = blockCol + warpCol + j * 8 + (lane & 3) * 2;
            if (r0 < M) {
                float2 v;
                v.x = fmaxf(c[i][j][0], 0.f);
                v.y = fmaxf(c[i][j][1], 0.f);
                *reinterpret_cast<float2*>(out + (size_t)r0 * D + col) = v;
            }
            if (r1 < M) {
                float2 v;
                v.x = fmaxf(c[i][j][2], 0.f);
                v.y = fmaxf(c[i][j][3], 0.f);
                *reinterpret_cast<float2*>(out + (size_t)r1 * D + col) = v;
            }
        }
    }
}

// ---------------------------------------------------------------------------
// kernel_launch
// ---------------------------------------------------------------------------
extern "C" void kernel_launch(void* const* d_in, const int* in_sizes, int n_in,
                              void* d_out, int out_size) {
    const float* h  = (const float*)d_in[0];
    const float* Wt = (const float*)d_in[1];
    const float* ew = (const float*)d_in[2];
    const void* src = d_in[3];
    const void* dst = d_in[4];
    float* out = (float*)d_out;

    int M = in_sizes[0] / D;
    int E = in_sizes[2];

    detect_idx_dtype<<<1, 1>>>((const unsigned*)src);
    convert_h<<<2048, 256>>>(h, (long long)M * ROW_U4);
    transpose_w_h<<<dim3(16, 16), dim3(32, 32)>>>(Wt);
    zero_cnt<<<(M + 255) / 256, 256>>>(M);
    hist_dst<<<(E + 255) / 256, 256>>>(dst, E);

    int sblocks = (M + SCAN_TILE - 1) / SCAN_TILE;
    scan_phase1<<<sblocks, SCAN_TILE>>>(M);
    scan_phase2<<<1, 32>>>(sblocks);
    scan_phase3<<<sblocks, SCAN_TILE>>>(M, E);

    reorder_edges<<<(E + 255) / 256, 256>>>(src, dst, ew, E);

    long long gthreads = (long long)M * 32;
    gather_agg<<<(int)((gthreads + 255) / 256), 256>>>(M);

    dim3 grid(D / BN, (M + BM - 1) / BM);
    gemm_relu<<<grid, 256>>>(out, M);
}

// round 10
// speedup vs baseline: 3.4175x; 1.0566x over previous
#include <cuda_runtime.h>
#include <cuda_fp16.h>
#include <cstdint>

#define D 512
#define ROW_U4 64         // uint4 per fp16 row (512*2B/16B)
#define MAX_NODES 100000
#define MAX_E 2000000
#define SCAN_TILE 1024
#define MAX_SCAN_BLOCKS 128

// fp16 copies (uint4-typed for alignment)
__device__ uint4 g_h2[(size_t)MAX_NODES * ROW_U4];     // h in fp16
__device__ uint4 g_agg_h[(size_t)MAX_NODES * ROW_U4];  // agg in fp16 (GEMM A)
__device__ uint4 g_wt_h[(size_t)D * D / 8];            // W^T fp16 [N][K]
__device__ int g_is64;
// CSR-by-dst structures
__device__ int   g_cnt[MAX_NODES];
__device__ int   g_off[MAX_NODES + 1];
__device__ int   g_cur[MAX_NODES];
__device__ int2  g_edge[MAX_E];   // (src, edge_weight bits) combined
__device__ int   g_bsum[MAX_SCAN_BLOCKS];

// Bit-cast helpers
__device__ __forceinline__ unsigned h2_to_u(__half2 h) {
    return *reinterpret_cast<unsigned*>(&h);
}
__device__ __forceinline__ __half2 u_to_h2(unsigned u) {
    return *reinterpret_cast<__half2*>(&u);
}
__device__ __forceinline__ void ldsm_x4(unsigned& r0, unsigned& r1,
                                        unsigned& r2, unsigned& r3,
                                        uint32_t addr) {
    asm volatile(
        "ldmatrix.sync.aligned.m8n8.x4.shared.b16 {%0,%1,%2,%3}, [%4];"
        : "=r"(r0), "=r"(r1), "=r"(r2), "=r"(r3) : "r"(addr));
}

// ---------------------------------------------------------------------------
__global__ void detect_idx_dtype(const unsigned* __restrict__ src_words) {
    int all_zero = 1;
    for (int i = 1; i < 64; i += 2)
        if (src_words[i] != 0u) all_zero = 0;
    g_is64 = all_zero;
}

// Convert h (fp32) -> g_h2 (fp16). One uint4 (8 halves) per thread-iter.
__global__ void convert_h(const float* __restrict__ h, long long n_u4) {
    long long i = blockIdx.x * (long long)blockDim.x + threadIdx.x;
    long long stride = gridDim.x * (long long)blockDim.x;
    for (; i < n_u4; i += stride) {
        const float4* p = reinterpret_cast<const float4*>(h + i * 8);
        float4 v0 = p[0], v1 = p[1];
        uint4 o;
        o.x = h2_to_u(__floats2half2_rn(v0.x, v0.y));
        o.y = h2_to_u(__floats2half2_rn(v0.z, v0.w));
        o.z = h2_to_u(__floats2half2_rn(v1.x, v1.y));
        o.w = h2_to_u(__floats2half2_rn(v1.z, v1.w));
        g_h2[i] = o;
    }
}

// Transpose W [K][N] fp32 -> g_wt_h [N][K] fp16.
__global__ void transpose_w_h(const float* __restrict__ W) {
    __shared__ float t[32][33];
    int bx = blockIdx.x * 32, by = blockIdx.y * 32;
    t[threadIdx.y][threadIdx.x] = W[(by + threadIdx.y) * D + bx + threadIdx.x];
    __syncthreads();
    __half* wt = reinterpret_cast<__half*>(g_wt_h);
    wt[(size_t)(bx + threadIdx.y) * D + by + threadIdx.x] =
        __float2half_rn(t[threadIdx.x][threadIdx.y]);
}

__global__ void zero_cnt(int M) {
    int i = blockIdx.x * blockDim.x + threadIdx.x;
    if (i < M) g_cnt[i] = 0;
}

__global__ void hist_dst(const void* __restrict__ dst_raw, int E) {
    int e = blockIdx.x * blockDim.x + threadIdx.x;
    if (e >= E) return;
    int d = g_is64 ? (int)reinterpret_cast<const long long*>(dst_raw)[e]
                   : reinterpret_cast<const int*>(dst_raw)[e];
    atomicAdd(&g_cnt[d], 1);
}

__global__ void scan_phase1(int M) {
    __shared__ int wsum[32];
    const int tid = threadIdx.x, lane = tid & 31, wid = tid >> 5;
    const int gi = blockIdx.x * SCAN_TILE + tid;

    int x = (gi < M) ? g_cnt[gi] : 0;

    int v = x;
#pragma unroll
    for (int d = 1; d < 32; d <<= 1) {
        int t = __shfl_up_sync(0xffffffffu, v, d);
        if (lane >= d) v += t;
    }
    if (lane == 31) wsum[wid] = v;
    __syncthreads();
    if (wid == 0) {
        int w = wsum[lane];
#pragma unroll
        for (int d = 1; d < 32; d <<= 1) {
            int t = __shfl_up_sync(0xffffffffu, w, d);
            if (lane >= d) w += t;
        }
        wsum[lane] = w;
    }
    __syncthreads();

    int excl = (v - x) + (wid > 0 ? wsum[wid - 1] : 0);
    if (gi < M) g_off[gi] = excl;
    if (tid == SCAN_TILE - 1) g_bsum[blockIdx.x] = excl + x;
}

__global__ void scan_phase2(int nblocks) {
    const int lane = threadIdx.x;
    int run = 0;
    for (int base = 0; base < nblocks; base += 32) {
        int i = base + lane;
        int x = (i < nblocks) ? g_bsum[i] : 0;
        int v = x;
#pragma unroll
        for (int d = 1; d < 32; d <<= 1) {
            int t = __shfl_up_sync(0xffffffffu, v, d);
            if (lane >= d) v += t;
        }
        if (i < nblocks) g_bsum[i] = run + (v - x);
        run += __shfl_sync(0xffffffffu, v, 31);
    }
}

__global__ void scan_phase3(int M, int E) {
    const int gi = blockIdx.x * SCAN_TILE + threadIdx.x;
    if (gi < M) {
        int o = g_off[gi] + g_bsum[blockIdx.x];
        g_off[gi] = o;
        g_cur[gi] = o;
    }
    if (gi == 0) g_off[M] = E;
}

__global__ void reorder_edges(const void* __restrict__ src_raw,
                              const void* __restrict__ dst_raw,
                              const float* __restrict__ ew, int E) {
    int e = blockIdx.x * blockDim.x + threadIdx.x;
    if (e >= E) return;
    int s, d;
    if (g_is64) {
        s = (int)reinterpret_cast<const long long*>(src_raw)[e];
        d = (int)reinterpret_cast<const long long*>(dst_raw)[e];
    } else {
        s = reinterpret_cast<const int*>(src_raw)[e];
        d = reinterpret_cast<const int*>(dst_raw)[e];
    }
    int pos = atomicAdd(&g_cur[d], 1);
    g_edge[pos] = make_int2(s, __float_as_int(ew[e]));
}

// ---------------------------------------------------------------------------
// Gather (fp16 rows): one warp per dst node. Per lane: 2 uint4 = 16 halves.
// ---------------------------------------------------------------------------
__device__ __forceinline__ void acc_u4(float2* acc, uint4 q, float w, int base) {
    float2 f;
    f = __half22float2(u_to_h2(q.x));
    acc[base + 0].x += f.x * w; acc[base + 0].y += f.y * w;
    f = __half22float2(u_to_h2(q.y));
    acc[base + 1].x += f.x * w; acc[base + 1].y += f.y * w;
    f = __half22float2(u_to_h2(q.z));
    acc[base + 2].x += f.x * w; acc[base + 2].y += f.y * w;
    f = __half22float2(u_to_h2(q.w));
    acc[base + 3].x += f.x * w; acc[base + 3].y += f.y * w;
}

__global__ void gather_agg(int M) {
    int node = (int)((blockIdx.x * (unsigned)blockDim.x + threadIdx.x) >> 5);
    if (node >= M) return;
    const int lane = threadIdx.x & 31;
    const int beg = g_off[node];
    const int end = g_off[node + 1];

    float2 acc[8];
#pragma unroll
    for (int i = 0; i < 8; i++) acc[i] = make_float2(0.f, 0.f);

    int e = beg;
    for (; e + 1 < end; e += 2) {
        int2 e0 = g_edge[e], e1 = g_edge[e + 1];
        float w0 = __int_as_float(e0.y), w1 = __int_as_float(e1.y);
        const uint4* p0 = g_h2 + (size_t)e0.x * ROW_U4 + lane * 2;
        const uint4* p1 = g_h2 + (size_t)e1.x * ROW_U4 + lane * 2;
        uint4 q00 = p0[0], q01 = p0[1];
        uint4 q10 = p1[0], q11 = p1[1];
        acc_u4(acc, q00, w0, 0); acc_u4(acc, q01, w0, 4);
        acc_u4(acc, q10, w1, 0); acc_u4(acc, q11, w1, 4);
    }
    if (e < end) {
        int2 e0 = g_edge[e];
        float w0 = __int_as_float(e0.y);
        const uint4* p0 = g_h2 + (size_t)e0.x * ROW_U4 + lane * 2;
        uint4 q00 = p0[0], q01 = p0[1];
        acc_u4(acc, q00, w0, 0); acc_u4(acc, q01, w0, 4);
    }

    uint4 o0, o1;
    o0.x = h2_to_u(__floats2half2_rn(acc[0].x, acc[0].y));
    o0.y = h2_to_u(__floats2half2_rn(acc[1].x, acc[1].y));
    o0.z = h2_to_u(__floats2half2_rn(acc[2].x, acc[2].y));
    o0.w = h2_to_u(__floats2half2_rn(acc[3].x, acc[3].y));
    o1.x = h2_to_u(__floats2half2_rn(acc[4].x, acc[4].y));
    o1.y = h2_to_u(__floats2half2_rn(acc[5].x, acc[5].y));
    o1.z = h2_to_u(__floats2half2_rn(acc[6].x, acc[6].y));
    o1.w = h2_to_u(__floats2half2_rn(acc[7].x, acc[7].y));
    uint4* o = g_agg_h + (size_t)node * ROW_U4 + lane * 2;
    o[0] = o0; o[1] = o1;
}

// ---------------------------------------------------------------------------
// fp16 mma.sync GEMM, DOUBLE-BUFFERED smem (one __syncthreads per kt).
// Block tile 128x256, BK=32, warp tile 64x64, m16n8k16, ldmatrix.x4.
// ---------------------------------------------------------------------------
#define BM 128
#define BN 256
#define BK 32
#define HS 20   // half2 stride per row
#define ABUF (BM * HS)
#define BBUF (BN * HS)

__global__ __launch_bounds__(256, 1)
void gemm_relu(float* __restrict__ out, int M) {
    __shared__ unsigned As[2][ABUF];   // 2 x 10 KB
    __shared__ unsigned Bs[2][BBUF];   // 2 x 20 KB

    const int tid  = threadIdx.x;
    const int warp = tid >> 5;
    const int lane = tid & 31;
    const int wm = warp & 1;          // 2 warps along M
    const int wn = warp >> 1;         // 4 warps along N
    const int warpRow = wm * 64;
    const int warpCol = wn * 64;
    const int blockRow = blockIdx.y * BM;
    const int blockCol = blockIdx.x * BN;

    const uint32_t as0 = (uint32_t)__cvta_generic_to_shared(&As[0][0]);
    const uint32_t bs0 = (uint32_t)__cvta_generic_to_shared(&Bs[0][0]);

    float c[4][8][4];
#pragma unroll
    for (int i = 0; i < 4; i++)
#pragma unroll
        for (int j = 0; j < 8; j++)
#pragma unroll
            for (int q = 0; q < 4; q++) c[i][j][q] = 0.f;

    uint4 aReg[2], bReg[4];

    auto loadTile = [&](int kt) {
#pragma unroll
        for (int wch = 0; wch < 2; wch++) {
            int idx = tid + wch * 256;
            int ra = idx >> 2, ca = idx & 3;
            int grow = blockRow + ra;
            if (grow < M)
                aReg[wch] = g_agg_h[(size_t)grow * ROW_U4 + kt * 4 + ca];
            else
                aReg[wch] = make_uint4(0u, 0u, 0u, 0u);
        }
#pragma unroll
        for (int wch = 0; wch < 4; wch++) {
            int idx = tid + wch * 256;
            int rb = idx >> 2, cb = idx & 3;
            bReg[wch] = g_wt_h[(size_t)(blockCol + rb) * (D / 8) + kt * 4 + cb];
        }
    };
    auto storeTile = [&](int b) {
#pragma unroll
        for (int wch = 0; wch < 2; wch++) {
            int idx = tid + wch * 256;
            int ra = idx >> 2, ca = idx & 3;
            unsigned* da = &As[b][ra * HS + ca * 4];
            uint4 v = aReg[wch];
            da[0] = v.x; da[1] = v.y; da[2] = v.z; da[3] = v.w;
        }
#pragma unroll
        for (int wch = 0; wch < 4; wch++) {
            int idx = tid + wch * 256;
            int rb = idx >> 2, cb = idx & 3;
            unsigned* db = &Bs[b][rb * HS + cb * 4];
            uint4 u = bReg[wch];
            db[0] = u.x; db[1] = u.y; db[2] = u.z; db[3] = u.w;
        }
    };

    // ldmatrix address components (constant across kt)
    const int a_row16 = lane & 15;
    const int a_khi   = (lane >> 4) << 2;
    const int b_row8  = lane & 7;
    const int b_jhi   = lane >> 4;
    const int b_khi   = ((lane >> 3) & 1) << 2;

    const int KT = D / BK;  // 16
    loadTile(0);
    storeTile(0);

    for (int kt = 0; kt < KT; kt++) {
        __syncthreads();                 // buffer kt&1 ready for all warps
        if (kt + 1 < KT) loadTile(kt + 1);   // LDG in flight under compute

        const int b = kt & 1;
        const uint32_t asb = as0 + (uint32_t)b * (ABUF * 4u);
        const uint32_t bsb = bs0 + (uint32_t)b * (BBUF * 4u);

#pragma unroll
        for (int ks = 0; ks < 2; ks++) {
            unsigned af[4][4], bf[8][2];
#pragma unroll
            for (int i = 0; i < 4; i++) {
                uint32_t addr = asb +
                    (((warpRow + i * 16 + a_row16) * HS) + ks * 8 + a_khi) * 4u;
                ldsm_x4(af[i][0], af[i][1], af[i][2], af[i][3], addr);
            }
#pragma unroll
            for (int jj = 0; jj < 4; jj++) {
                int j = jj * 2;
                uint32_t addr = bsb +
                    (((warpCol + (j + b_jhi) * 8 + b_row8) * HS) + ks * 8 + b_khi) * 4u;
                ldsm_x4(bf[j][0], bf[j][1], bf[j + 1][0], bf[j + 1][1], addr);
            }
#pragma unroll
            for (int i = 0; i < 4; i++)
#pragma unroll
                for (int j = 0; j < 8; j++) {
                    asm volatile(
                        "mma.sync.aligned.m16n8k16.row.col.f32.f16.f16.f32 "
                        "{%0,%1,%2,%3}, {%4,%5,%6,%7}, {%8,%9}, {%0,%1,%2,%3};"
                        : "+f"(c[i][j][0]), "+f"(c[i][j][1]),
                          "+f"(c[i][j][2]), "+f"(c[i][j][3])
                        : "r"(af[i][0]), "r"(af[i][1]),
                          "r"(af[i][2]), "r"(af[i][3]),
                          "r"(bf[j][0]), "r"(bf[j][1]));
                }
        }
        if (kt + 1 < KT) storeTile((kt + 1) & 1);  // other buffer: no race
    }

    // Epilogue: ReLU + store
#pragma unroll
    for (int i = 0; i < 4; i++) {
        int r0 = blockRow + warpRow + i * 16 + (lane >> 2);
        int r1 = r0 + 8;
#pragma unroll
        for (int j = 0; j < 8; j++) {
            int col = blockCol + warpCol + j * 8 + (lane & 3) * 2;
            if (r0 < M) {
                float2 v;
                v.x = fmaxf(c[i][j][0], 0.f);
                v.y = fmaxf(c[i][j][1], 0.f);
                *reinterpret_cast<float2*>(out + (size_t)r0 * D + col) = v;
            }
            if (r1 < M) {
                float2 v;
                v.x = fmaxf(c[i][j][2], 0.f);
                v.y = fmaxf(c[i][j][3], 0.f);
                *reinterpret_cast<float2*>(out + (size_t)r1 * D + col) = v;
            }
        }
    }
}

// ---------------------------------------------------------------------------
// kernel_launch: fork-join stream overlap of the two independent
// preprocessing chains (capture-legal event fork pattern).
// ---------------------------------------------------------------------------
extern "C" void kernel_launch(void* const* d_in, const int* in_sizes, int n_in,
                              void* d_out, int out_size) {
    const float* h  = (const float*)d_in[0];
    const float* Wt = (const float*)d_in[1];
    const float* ew = (const float*)d_in[2];
    const void* src = d_in[3];
    const void* dst = d_in[4];
    float* out = (float*)d_out;

    int M = in_sizes[0] / D;
    int E = in_sizes[2];

    static cudaStream_t s2 = nullptr;
    static cudaEvent_t evFork = nullptr, evJoin = nullptr;
    if (s2 == nullptr) {
        cudaStreamCreateWithFlags(&s2, cudaStreamNonBlocking);
        cudaEventCreateWithFlags(&evFork, cudaEventDisableTiming);
        cudaEventCreateWithFlags(&evJoin, cudaEventDisableTiming);
    }

    detect_idx_dtype<<<1, 1>>>((const unsigned*)src);

    // fork: CSR chain on s2, fp16 conversions on the capture stream
    cudaEventRecord(evFork, 0);
    cudaStreamWaitEvent(s2, evFork, 0);

    zero_cnt<<<(M + 255) / 256, 256, 0, s2>>>(M);
    hist_dst<<<(E + 255) / 256, 256, 0, s2>>>(dst, E);
    int sblocks = (M + SCAN_TILE - 1) / SCAN_TILE;
    scan_phase1<<<sblocks, SCAN_TILE, 0, s2>>>(M);
    scan_phase2<<<1, 32, 0, s2>>>(sblocks);
    scan_phase3<<<sblocks, SCAN_TILE, 0, s2>>>(M, E);
    reorder_edges<<<(E + 255) / 256, 256, 0, s2>>>(src, dst, ew, E);
    cudaEventRecord(evJoin, s2);

    convert_h<<<2048, 256>>>(h, (long long)M * ROW_U4);
    transpose_w_h<<<dim3(16, 16), dim3(32, 32)>>>(Wt);

    // join
    cudaStreamWaitEvent(0, evJoin, 0);

    long long gthreads = (long long)M * 32;
    gather_agg<<<(int)((gthreads + 255) / 256), 256>>>(M);

    dim3 grid(D / BN, (M + BM - 1) / BM);
    gemm_relu<<<grid, 256>>>(out, M);
}